// round 1
// baseline (speedup 1.0000x reference)
#include <cuda_runtime.h>
#include <cuda_bf16.h>
#include <cstdint>

using bf16 = __nv_bfloat16;

#define T_TOK 8192
#define HDIM  2048
#define FDIM  4096
#define NEXP  8

// ---------------- scratch (device globals: allocation-free rule) ----------------
__device__ int   g_cnt[NEXP];
__device__ int   g_list[NEXP][T_TOK];
__device__ float g_wt[NEXP][T_TOK];
__device__ float g_act[(size_t)T_TOK * FDIM];   // 134 MB expert-local activations

// ---------------- helpers ----------------
__device__ __forceinline__ uint32_t sm_addr(const void* p) {
    return (uint32_t)__cvta_generic_to_shared(p);
}

__device__ __forceinline__ void ldsm_x4(uint32_t* r, const void* p) {
    uint32_t a = sm_addr(p);
    asm volatile("ldmatrix.sync.aligned.m8n8.x4.shared.b16 {%0,%1,%2,%3}, [%4];\n"
                 : "=r"(r[0]), "=r"(r[1]), "=r"(r[2]), "=r"(r[3]) : "r"(a));
}

__device__ __forceinline__ void mma_bf16(float* d, const uint32_t* a, const uint32_t* b) {
    asm volatile(
        "mma.sync.aligned.m16n8k16.row.col.f32.bf16.bf16.f32 "
        "{%0,%1,%2,%3}, {%4,%5,%6,%7}, {%8,%9}, {%0,%1,%2,%3};\n"
        : "+f"(d[0]), "+f"(d[1]), "+f"(d[2]), "+f"(d[3])
        : "r"(a[0]), "r"(a[1]), "r"(a[2]), "r"(a[3]), "r"(b[0]), "r"(b[1]));
}

__device__ __forceinline__ uint32_t pack2(bf16 a, bf16 b) {
    union { __nv_bfloat162 v; uint32_t u; } t;
    t.v.x = a; t.v.y = b;
    return t.u;
}

// split fp32x4 into bf16 hi/lo planes and store 8B each
__device__ __forceinline__ void split_store(bf16* hi, bf16* lo, float4 v) {
    float f0 = v.x, f1 = v.y, f2 = v.z, f3 = v.w;
    bf16 h0 = __float2bfloat16_rn(f0);
    bf16 h1 = __float2bfloat16_rn(f1);
    bf16 h2 = __float2bfloat16_rn(f2);
    bf16 h3 = __float2bfloat16_rn(f3);
    bf16 l0 = __float2bfloat16_rn(f0 - __bfloat162float(h0));
    bf16 l1 = __float2bfloat16_rn(f1 - __bfloat162float(h1));
    bf16 l2 = __float2bfloat16_rn(f2 - __bfloat162float(h2));
    bf16 l3 = __float2bfloat16_rn(f3 - __bfloat162float(h3));
    *reinterpret_cast<uint2*>(hi) = make_uint2(pack2(h0, h1), pack2(h2, h3));
    *reinterpret_cast<uint2*>(lo) = make_uint2(pack2(l0, l1), pack2(l2, l3));
}

// ---------------- reset ----------------
__global__ void reset_kernel() {
    if (threadIdx.x < NEXP) g_cnt[threadIdx.x] = 0;
}

// ---------------- router: logits + softmax + top2 + bucket scatter ----------------
__global__ void __launch_bounds__(256) router_kernel(
    const float* __restrict__ X, const float* __restrict__ RW,
    const float* __restrict__ RB, float* __restrict__ LOG)
{
    __shared__ float sx[HDIM];
    __shared__ float slog[NEXP];
    const int t   = blockIdx.x;
    const int tid = threadIdx.x;

    for (int i = tid; i < HDIM; i += 256) sx[i] = X[(size_t)t * HDIM + i];
    __syncthreads();

    const int w = tid >> 5, lane = tid & 31;
    float s = 0.f;
    const float* rw = RW + (size_t)w * HDIM;
    for (int i = lane; i < HDIM; i += 32) s += sx[i] * rw[i];
    #pragma unroll
    for (int off = 16; off > 0; off >>= 1) s += __shfl_xor_sync(0xffffffffu, s, off);
    if (lane == 0) slog[w] = s + RB[w];
    __syncthreads();

    if (tid == 0) {
        float l[NEXP];
        float m = -1e30f;
        #pragma unroll
        for (int e = 0; e < NEXP; e++) {
            l[e] = slog[e];
            LOG[(size_t)t * NEXP + e] = l[e];
            m = fmaxf(m, l[e]);
        }
        float p[NEXP];
        #pragma unroll
        for (int e = 0; e < NEXP; e++) p[e] = __expf(l[e] - m);
        int i0 = 0;
        #pragma unroll
        for (int e = 1; e < NEXP; e++) if (l[e] > l[i0]) i0 = e;
        int i1 = -1;
        #pragma unroll
        for (int e = 0; e < NEXP; e++) {
            if (e == i0) continue;
            if (i1 < 0 || l[e] > l[i1]) i1 = e;
        }
        float ws = p[i0] + p[i1];
        float w0 = p[i0] / ws, w1 = p[i1] / ws;
        int p0 = atomicAdd(&g_cnt[i0], 1);
        g_list[i0][p0] = t; g_wt[i0][p0] = w0;
        int p1 = atomicAdd(&g_cnt[i1], 1);
        g_list[i1][p1] = t; g_wt[i1][p1] = w1;
    }
}

// ---------------- GEMM13: act = silu(X w1^T) * (X w3^T), gathered rows ----------------
// BM=128, BN=64, BK=32; 256 threads (8 warps: 4 in M x 2 in N)
__global__ void __launch_bounds__(256) gemm13_kernel(
    const float* __restrict__ X,
    const float* __restrict__ W1,
    const float* __restrict__ W3,
    int e)
{
    const int count = (e < 0) ? T_TOK : g_cnt[e];
    const int m0 = blockIdx.y * 128;
    if (m0 >= count) return;
    const int n0 = blockIdx.x * 64;

    __shared__ __align__(16) bf16 sAh[128][40];
    __shared__ __align__(16) bf16 sAl[128][40];
    __shared__ __align__(16) bf16 sB1h[64][40];
    __shared__ __align__(16) bf16 sB1l[64][40];
    __shared__ __align__(16) bf16 sB3h[64][40];
    __shared__ __align__(16) bf16 sB3l[64][40];

    const int tid  = threadIdx.x;
    const int lane = tid & 31;
    const int warp = tid >> 5;
    const int wm = (warp & 3) * 32;
    const int wn = (warp >> 2) * 32;

    const float* aptr[4]; int arow[4]; int acol[4]; bool aval[4];
    #pragma unroll
    for (int i = 0; i < 4; i++) {
        int lin = tid + i * 256;
        int r = lin >> 3;
        int c = (lin & 7) * 4;
        int gr = m0 + r;
        bool v = gr < count;
        int tok = 0;
        if (v) tok = (e < 0) ? gr : g_list[e][gr];
        aptr[i] = X + (size_t)tok * HDIM + c;
        arow[i] = r; acol[i] = c; aval[i] = v;
    }
    const float* b1ptr[2]; const float* b3ptr[2]; int brow[2]; int bcol[2];
    #pragma unroll
    for (int i = 0; i < 2; i++) {
        int lin = tid + i * 256;
        int r = lin >> 3;
        int c = (lin & 7) * 4;
        b1ptr[i] = W1 + (size_t)(n0 + r) * HDIM + c;
        b3ptr[i] = W3 + (size_t)(n0 + r) * HDIM + c;
        brow[i] = r; bcol[i] = c;
    }

    float acc1[2][4][4];
    float acc3[2][4][4];
    #pragma unroll
    for (int i = 0; i < 2; i++)
        #pragma unroll
        for (int j = 0; j < 4; j++)
            #pragma unroll
            for (int q = 0; q < 4; q++) { acc1[i][j][q] = 0.f; acc3[i][j][q] = 0.f; }

    const int a_r = (lane & 7) + ((lane >> 3) & 1) * 8;
    const int a_c = ((lane >> 4) & 1) * 8;
    const int b_r = (lane & 7) + ((lane >> 4) & 1) * 8;
    const int b_c = ((lane >> 3) & 1) * 8;

    for (int k0 = 0; k0 < HDIM; k0 += 32) {
        #pragma unroll
        for (int i = 0; i < 4; i++) {
            float4 v = aval[i] ? *(const float4*)(aptr[i] + k0)
                               : make_float4(0.f, 0.f, 0.f, 0.f);
            split_store(&sAh[arow[i]][acol[i]], &sAl[arow[i]][acol[i]], v);
        }
        #pragma unroll
        for (int i = 0; i < 2; i++) {
            float4 v1 = *(const float4*)(b1ptr[i] + k0);
            split_store(&sB1h[brow[i]][bcol[i]], &sB1l[brow[i]][bcol[i]], v1);
            float4 v3 = *(const float4*)(b3ptr[i] + k0);
            split_store(&sB3h[brow[i]][bcol[i]], &sB3l[brow[i]][bcol[i]], v3);
        }
        __syncthreads();

        #pragma unroll
        for (int kk = 0; kk < 32; kk += 16) {
            uint32_t ah[2][4], al[2][4];
            ldsm_x4(ah[0], &sAh[wm +      a_r][kk + a_c]);
            ldsm_x4(ah[1], &sAh[wm + 16 + a_r][kk + a_c]);
            ldsm_x4(al[0], &sAl[wm +      a_r][kk + a_c]);
            ldsm_x4(al[1], &sAl[wm + 16 + a_r][kk + a_c]);
            uint32_t b1h[8], b1l[8], b3h[8], b3l[8];
            #pragma unroll
            for (int p = 0; p < 2; p++) {
                int nb = wn + p * 16;
                ldsm_x4(&b1h[p * 4], &sB1h[nb + b_r][kk + b_c]);
                ldsm_x4(&b1l[p * 4], &sB1l[nb + b_r][kk + b_c]);
                ldsm_x4(&b3h[p * 4], &sB3h[nb + b_r][kk + b_c]);
                ldsm_x4(&b3l[p * 4], &sB3l[nb + b_r][kk + b_c]);
            }
            // hi*hi
            #pragma unroll
            for (int mi = 0; mi < 2; mi++)
                #pragma unroll
                for (int ni = 0; ni < 4; ni++) mma_bf16(acc1[mi][ni], ah[mi], &b1h[ni * 2]);
            #pragma unroll
            for (int mi = 0; mi < 2; mi++)
                #pragma unroll
                for (int ni = 0; ni < 4; ni++) mma_bf16(acc3[mi][ni], ah[mi], &b3h[ni * 2]);
            // hi*lo
            #pragma unroll
            for (int mi = 0; mi < 2; mi++)
                #pragma unroll
                for (int ni = 0; ni < 4; ni++) mma_bf16(acc1[mi][ni], ah[mi], &b1l[ni * 2]);
            #pragma unroll
            for (int mi = 0; mi < 2; mi++)
                #pragma unroll
                for (int ni = 0; ni < 4; ni++) mma_bf16(acc3[mi][ni], ah[mi], &b3l[ni * 2]);
            // lo*hi
            #pragma unroll
            for (int mi = 0; mi < 2; mi++)
                #pragma unroll
                for (int ni = 0; ni < 4; ni++) mma_bf16(acc1[mi][ni], al[mi], &b1h[ni * 2]);
            #pragma unroll
            for (int mi = 0; mi < 2; mi++)
                #pragma unroll
                for (int ni = 0; ni < 4; ni++) mma_bf16(acc3[mi][ni], al[mi], &b3h[ni * 2]);
        }
        __syncthreads();
    }

    // epilogue: silu(acc1) * acc3 -> g_act
    #pragma unroll
    for (int mi = 0; mi < 2; mi++) {
        #pragma unroll
        for (int q2 = 0; q2 < 2; q2++) {
            int r_loc = m0 + wm + mi * 16 + (lane >> 2) + q2 * 8;
            if (r_loc >= count) continue;
            float* actrow = g_act + (size_t)r_loc * FDIM;
            #pragma unroll
            for (int ni = 0; ni < 4; ni++) {
                #pragma unroll
                for (int q1 = 0; q1 < 2; q1++) {
                    int c = n0 + wn + ni * 8 + (lane & 3) * 2 + q1;
                    float a = acc1[mi][ni][q2 * 2 + q1];
                    float b = acc3[mi][ni][q2 * 2 + q1];
                    float sl = a / (1.f + __expf(-a));
                    actrow[c] = sl * b;
                }
            }
        }
    }
}

// ---------------- GEMM2: out += w * (act @ w2^T), scattered rows ----------------
// BM=128, BN=128, BK=32; 256 threads (8 warps: 4 in M x 2 in N, warp tile 32x64)
__global__ void __launch_bounds__(256) gemm2_kernel(
    const float* __restrict__ W2,
    float* __restrict__ OUT,
    int e)
{
    const int count = (e < 0) ? T_TOK : g_cnt[e];
    const int m0 = blockIdx.y * 128;
    if (m0 >= count) return;
    const int n0 = blockIdx.x * 128;

    __shared__ __align__(16) bf16 sAh[128][40];
    __shared__ __align__(16) bf16 sAl[128][40];
    __shared__ __align__(16) bf16 sBh[128][40];
    __shared__ __align__(16) bf16 sBl[128][40];

    const int tid  = threadIdx.x;
    const int lane = tid & 31;
    const int warp = tid >> 5;
    const int wm = (warp & 3) * 32;
    const int wn = (warp >> 2) * 64;

    const float* aptr[4]; int arow[4]; int acol[4]; bool aval[4];
    #pragma unroll
    for (int i = 0; i < 4; i++) {
        int lin = tid + i * 256;
        int r = lin >> 3;
        int c = (lin & 7) * 4;
        int gr = m0 + r;
        bool v = gr < count;
        aptr[i] = g_act + (size_t)(v ? gr : 0) * FDIM + c;
        arow[i] = r; acol[i] = c; aval[i] = v;
    }
    const float* bptr[4]; int brow[4]; int bcol[4];
    #pragma unroll
    for (int i = 0; i < 4; i++) {
        int lin = tid + i * 256;
        int r = lin >> 3;
        int c = (lin & 7) * 4;
        bptr[i] = W2 + (size_t)(n0 + r) * FDIM + c;
        brow[i] = r; bcol[i] = c;
    }

    float acc[2][8][4];
    #pragma unroll
    for (int i = 0; i < 2; i++)
        #pragma unroll
        for (int j = 0; j < 8; j++)
            #pragma unroll
            for (int q = 0; q < 4; q++) acc[i][j][q] = 0.f;

    const int a_r = (lane & 7) + ((lane >> 3) & 1) * 8;
    const int a_c = ((lane >> 4) & 1) * 8;
    const int b_r = (lane & 7) + ((lane >> 4) & 1) * 8;
    const int b_c = ((lane >> 3) & 1) * 8;

    for (int k0 = 0; k0 < FDIM; k0 += 32) {
        #pragma unroll
        for (int i = 0; i < 4; i++) {
            float4 v = aval[i] ? *(const float4*)(aptr[i] + k0)
                               : make_float4(0.f, 0.f, 0.f, 0.f);
            split_store(&sAh[arow[i]][acol[i]], &sAl[arow[i]][acol[i]], v);
        }
        #pragma unroll
        for (int i = 0; i < 4; i++) {
            float4 v = *(const float4*)(bptr[i] + k0);
            split_store(&sBh[brow[i]][bcol[i]], &sBl[brow[i]][bcol[i]], v);
        }
        __syncthreads();

        #pragma unroll
        for (int kk = 0; kk < 32; kk += 16) {
            uint32_t ah[2][4], al[2][4];
            ldsm_x4(ah[0], &sAh[wm +      a_r][kk + a_c]);
            ldsm_x4(ah[1], &sAh[wm + 16 + a_r][kk + a_c]);
            ldsm_x4(al[0], &sAl[wm +      a_r][kk + a_c]);
            ldsm_x4(al[1], &sAl[wm + 16 + a_r][kk + a_c]);
            uint32_t bh[16], bl[16];
            #pragma unroll
            for (int p = 0; p < 4; p++) {
                int nb = wn + p * 16;
                ldsm_x4(&bh[p * 4], &sBh[nb + b_r][kk + b_c]);
                ldsm_x4(&bl[p * 4], &sBl[nb + b_r][kk + b_c]);
            }
            #pragma unroll
            for (int mi = 0; mi < 2; mi++)
                #pragma unroll
                for (int ni = 0; ni < 8; ni++) mma_bf16(acc[mi][ni], ah[mi], &bh[ni * 2]);
            #pragma unroll
            for (int mi = 0; mi < 2; mi++)
                #pragma unroll
                for (int ni = 0; ni < 8; ni++) mma_bf16(acc[mi][ni], ah[mi], &bl[ni * 2]);
            #pragma unroll
            for (int mi = 0; mi < 2; mi++)
                #pragma unroll
                for (int ni = 0; ni < 8; ni++) mma_bf16(acc[mi][ni], al[mi], &bh[ni * 2]);
        }
        __syncthreads();
    }

    // epilogue
    #pragma unroll
    for (int mi = 0; mi < 2; mi++) {
        #pragma unroll
        for (int q2 = 0; q2 < 2; q2++) {
            int r_loc = m0 + wm + mi * 16 + (lane >> 2) + q2 * 8;
            if (r_loc >= count) continue;
            if (e < 0) {
                float* orow = OUT + (size_t)r_loc * HDIM;
                #pragma unroll
                for (int ni = 0; ni < 8; ni++) {
                    #pragma unroll
                    for (int q1 = 0; q1 < 2; q1++) {
                        int c = n0 + wn + ni * 8 + (lane & 3) * 2 + q1;
                        orow[c] = acc[mi][ni][q2 * 2 + q1];
                    }
                }
            } else {
                int tok = g_list[e][r_loc];
                float wgt = g_wt[e][r_loc];
                float* orow = OUT + (size_t)tok * HDIM;
                #pragma unroll
                for (int ni = 0; ni < 8; ni++) {
                    #pragma unroll
                    for (int q1 = 0; q1 < 2; q1++) {
                        int c = n0 + wn + ni * 8 + (lane & 3) * 2 + q1;
                        atomicAdd(&orow[c], wgt * acc[mi][ni][q2 * 2 + q1]);
                    }
                }
            }
        }
    }
}

// ---------------- launch ----------------
extern "C" void kernel_launch(void* const* d_in, const int* in_sizes, int n_in,
                              void* d_out, int out_size)
{
    const float* x   = (const float*)d_in[0];
    const float* rw  = (const float*)d_in[1];
    const float* rb  = (const float*)d_in[2];
    const float* w1  = (const float*)d_in[3];
    const float* w2  = (const float*)d_in[4];
    const float* w3  = (const float*)d_in[5];
    const float* sw1 = (const float*)d_in[6];
    const float* sw2 = (const float*)d_in[7];
    const float* sw3 = (const float*)d_in[8];

    float* out    = (float*)d_out;
    float* logits = out + (size_t)T_TOK * HDIM;

    reset_kernel<<<1, 32>>>();
    router_kernel<<<T_TOK, 256>>>(x, rw, rb, logits);

    dim3 g13(FDIM / 64, T_TOK / 128);   // 64 x 64
    dim3 g2(HDIM / 128, T_TOK / 128);   // 16 x 64

    // shared expert first: plain stores initialize every cell of `out`
    gemm13_kernel<<<g13, 256>>>(x, sw1, sw3, -1);
    gemm2_kernel<<<g2, 256>>>(sw2, out, -1);

    const size_t estride = (size_t)FDIM * HDIM;
    for (int e = 0; e < NEXP; e++) {
        gemm13_kernel<<<g13, 256>>>(x, w1 + (size_t)e * estride, w3 + (size_t)e * estride, e);
        gemm2_kernel<<<g2, 256>>>(w2 + (size_t)e * estride, out, e);
    }
}

// round 2
// speedup vs baseline: 2.2369x; 2.2369x over previous
#include <cuda_runtime.h>
#include <cuda_bf16.h>
#include <cstdint>

using bf16 = __nv_bfloat16;

#define T_TOK 8192
#define HDIM  2048
#define FDIM  4096
#define NEXP  8
#define BK    32

static const size_t WSZ = (size_t)FDIM * HDIM;   // one expert weight matrix

// ---------------- persistent scratch (device globals) ----------------
__device__ int   g_cnt[NEXP];
__device__ int   g_list[NEXP][T_TOK];
__device__ float g_wt[NEXP][T_TOK];

// bf16 hi/lo planes
__device__ bf16 g_xh[(size_t)T_TOK * HDIM];
__device__ bf16 g_xl[(size_t)T_TOK * HDIM];
__device__ bf16 g_w1h[9 * (size_t)FDIM * HDIM];
__device__ bf16 g_w1l[9 * (size_t)FDIM * HDIM];
__device__ bf16 g_w3h[9 * (size_t)FDIM * HDIM];
__device__ bf16 g_w3l[9 * (size_t)FDIM * HDIM];
__device__ bf16 g_w2h[9 * (size_t)FDIM * HDIM];
__device__ bf16 g_w2l[9 * (size_t)FDIM * HDIM];
__device__ bf16 g_acth[(size_t)T_TOK * FDIM];
__device__ bf16 g_actl[(size_t)T_TOK * FDIM];

// ---------------- helpers ----------------
__device__ __forceinline__ uint32_t sm_addr(const void* p) {
    return (uint32_t)__cvta_generic_to_shared(p);
}

__device__ __forceinline__ void ldsm_x4(uint32_t* r, const bf16* p) {
    uint32_t a = sm_addr(p);
    asm volatile("ldmatrix.sync.aligned.m8n8.x4.shared.b16 {%0,%1,%2,%3}, [%4];\n"
                 : "=r"(r[0]), "=r"(r[1]), "=r"(r[2]), "=r"(r[3]) : "r"(a));
}

__device__ __forceinline__ void mma_bf16(float* d, const uint32_t* a, const uint32_t* b) {
    asm volatile(
        "mma.sync.aligned.m16n8k16.row.col.f32.bf16.bf16.f32 "
        "{%0,%1,%2,%3}, {%4,%5,%6,%7}, {%8,%9}, {%0,%1,%2,%3};\n"
        : "+f"(d[0]), "+f"(d[1]), "+f"(d[2]), "+f"(d[3])
        : "r"(a[0]), "r"(a[1]), "r"(a[2]), "r"(a[3]), "r"(b[0]), "r"(b[1]));
}

__device__ __forceinline__ uint32_t pack2(bf16 a, bf16 b) {
    union { __nv_bfloat162 v; uint32_t u; } t;
    t.v.x = a; t.v.y = b;
    return t.u;
}

__device__ __forceinline__ void cp16(bf16* dst, const bf16* src, bool valid) {
    uint32_t d = sm_addr(dst);
    int sz = valid ? 16 : 0;
    asm volatile("cp.async.cg.shared.global [%0], [%1], 16, %2;\n"
                 :: "r"(d), "l"(src), "r"(sz));
}
#define CP_COMMIT() asm volatile("cp.async.commit_group;\n" ::: "memory")
#define CP_WAIT(n)  asm volatile("cp.async.wait_group %0;\n" :: "n"(n) : "memory")

// ---------------- split fp32 array -> bf16 hi/lo planes ----------------
__global__ void __launch_bounds__(256) split_arr(
    const float* __restrict__ src, bf16* __restrict__ hi, bf16* __restrict__ lo, size_t n4)
{
    size_t i = blockIdx.x * (size_t)blockDim.x + threadIdx.x;
    size_t stride = (size_t)gridDim.x * blockDim.x;
    const float4* s4 = (const float4*)src;
    for (; i < n4; i += stride) {
        float4 v = s4[i];
        bf16 h0 = __float2bfloat16_rn(v.x);
        bf16 h1 = __float2bfloat16_rn(v.y);
        bf16 h2 = __float2bfloat16_rn(v.z);
        bf16 h3 = __float2bfloat16_rn(v.w);
        bf16 l0 = __float2bfloat16_rn(v.x - __bfloat162float(h0));
        bf16 l1 = __float2bfloat16_rn(v.y - __bfloat162float(h1));
        bf16 l2 = __float2bfloat16_rn(v.z - __bfloat162float(h2));
        bf16 l3 = __float2bfloat16_rn(v.w - __bfloat162float(h3));
        *reinterpret_cast<uint2*>(hi + i * 4) = make_uint2(pack2(h0, h1), pack2(h2, h3));
        *reinterpret_cast<uint2*>(lo + i * 4) = make_uint2(pack2(l0, l1), pack2(l2, l3));
    }
}

// ---------------- reset ----------------
__global__ void reset_kernel() {
    if (threadIdx.x < NEXP) g_cnt[threadIdx.x] = 0;
}

// ---------------- router ----------------
__global__ void __launch_bounds__(256) router_kernel(
    const float* __restrict__ X, const float* __restrict__ RW,
    const float* __restrict__ RB, float* __restrict__ LOG)
{
    __shared__ float sx[HDIM];
    __shared__ float slog[NEXP];
    const int t   = blockIdx.x;
    const int tid = threadIdx.x;

    for (int i = tid; i < HDIM; i += 256) sx[i] = X[(size_t)t * HDIM + i];
    __syncthreads();

    const int w = tid >> 5, lane = tid & 31;
    float s = 0.f;
    const float* rw = RW + (size_t)w * HDIM;
    for (int i = lane; i < HDIM; i += 32) s += sx[i] * rw[i];
    #pragma unroll
    for (int off = 16; off > 0; off >>= 1) s += __shfl_xor_sync(0xffffffffu, s, off);
    if (lane == 0) slog[w] = s + RB[w];
    __syncthreads();

    if (tid == 0) {
        float l[NEXP];
        float m = -1e30f;
        #pragma unroll
        for (int e = 0; e < NEXP; e++) {
            l[e] = slog[e];
            LOG[(size_t)t * NEXP + e] = l[e];
            m = fmaxf(m, l[e]);
        }
        float p[NEXP];
        #pragma unroll
        for (int e = 0; e < NEXP; e++) p[e] = __expf(l[e] - m);
        int i0 = 0;
        #pragma unroll
        for (int e = 1; e < NEXP; e++) if (l[e] > l[i0]) i0 = e;
        int i1 = -1;
        #pragma unroll
        for (int e = 0; e < NEXP; e++) {
            if (e == i0) continue;
            if (i1 < 0 || l[e] > l[i1]) i1 = e;
        }
        float ws = p[i0] + p[i1];
        float w0 = p[i0] / ws, w1 = p[i1] / ws;
        int p0 = atomicAdd(&g_cnt[i0], 1);
        g_list[i0][p0] = t; g_wt[i0][p0] = w0;
        int p1 = atomicAdd(&g_cnt[i1], 1);
        g_list[i1][p1] = t; g_wt[i1][p1] = w1;
    }
}

// ---------------- GEMM13: act = silu(X w1^T) * (X w3^T), gathered rows ----------------
// BM=128, BN=64, BK=32, 2-stage cp.async pipeline; 8 warps (4 M x 2 N)
// smem stage layout (bf16 elems): Ah 0, Al 5120, B1h 10240, B1l 12800, B3h 15360, B3l 17920
#define ST13 20480
__global__ void __launch_bounds__(256) gemm13_kernel(int e)
{
    const int count = (e == NEXP) ? T_TOK : g_cnt[e];
    const int m0 = blockIdx.y * 128;
    if (m0 >= count) return;
    const int n0 = blockIdx.x * 64;

    extern __shared__ __align__(16) bf16 sm[];

    const bf16* W1h = g_w1h + (size_t)e * WSZ;
    const bf16* W1l = g_w1l + (size_t)e * WSZ;
    const bf16* W3h = g_w3h + (size_t)e * WSZ;
    const bf16* W3l = g_w3l + (size_t)e * WSZ;

    const int tid  = threadIdx.x;
    const int lane = tid & 31;
    const int warp = tid >> 5;
    const int wm = (warp & 3) * 32;
    const int wn = (warp >> 2) * 32;

    // A chunks: 2 per thread per plane
    const bf16* srcAh[2]; const bf16* srcAl[2]; int aoff[2]; bool aval[2];
    #pragma unroll
    for (int i = 0; i < 2; i++) {
        int cidx = tid + i * 256;
        int r = cidx >> 2;
        int c8 = (cidx & 3) * 8;
        int gr = m0 + r;
        bool v = gr < count;
        int tok = 0;
        if (v) tok = (e == NEXP) ? gr : g_list[e][gr];
        srcAh[i] = g_xh + (size_t)tok * HDIM + c8;
        srcAl[i] = g_xl + (size_t)tok * HDIM + c8;
        aoff[i]  = r * 40 + c8;
        aval[i]  = v;
    }
    // B chunks: 1 per thread per plane per matrix
    const int br = tid >> 2;
    const int bc8 = (tid & 3) * 8;
    const size_t bsrc = (size_t)(n0 + br) * HDIM + bc8;
    const int boff = br * 40 + bc8;

    float acc1[2][4][4];
    float acc3[2][4][4];
    #pragma unroll
    for (int i = 0; i < 2; i++)
        #pragma unroll
        for (int j = 0; j < 4; j++)
            #pragma unroll
            for (int q = 0; q < 4; q++) { acc1[i][j][q] = 0.f; acc3[i][j][q] = 0.f; }

    const int a_r = (lane & 7) + ((lane >> 3) & 1) * 8;
    const int a_c = ((lane >> 4) & 1) * 8;
    const int b_r = (lane & 7) + ((lane >> 4) & 1) * 8;
    const int b_c = ((lane >> 3) & 1) * 8;

    const int KT = HDIM / BK;

    // stage loader
    auto load_stage = [&](int s, int k0) {
        bf16* base = sm + s * ST13;
        #pragma unroll
        for (int i = 0; i < 2; i++) {
            cp16(base +         aoff[i], srcAh[i] + k0, aval[i]);
            cp16(base +  5120 + aoff[i], srcAl[i] + k0, aval[i]);
        }
        cp16(base + 10240 + boff, W1h + bsrc + k0, true);
        cp16(base + 12800 + boff, W1l + bsrc + k0, true);
        cp16(base + 15360 + boff, W3h + bsrc + k0, true);
        cp16(base + 17920 + boff, W3l + bsrc + k0, true);
    };

    load_stage(0, 0);
    CP_COMMIT();

    for (int kt = 0; kt < KT; kt++) {
        if (kt + 1 < KT) {
            load_stage((kt + 1) & 1, (kt + 1) * BK);
            CP_COMMIT();
            CP_WAIT(1);
        } else {
            CP_WAIT(0);
        }
        __syncthreads();
        const bf16* base = sm + (kt & 1) * ST13;

        #pragma unroll
        for (int kk = 0; kk < 32; kk += 16) {
            uint32_t ah[2][4], al[2][4];
            ldsm_x4(ah[0], base +        (wm +      a_r) * 40 + kk + a_c);
            ldsm_x4(ah[1], base +        (wm + 16 + a_r) * 40 + kk + a_c);
            ldsm_x4(al[0], base + 5120 + (wm +      a_r) * 40 + kk + a_c);
            ldsm_x4(al[1], base + 5120 + (wm + 16 + a_r) * 40 + kk + a_c);
            uint32_t b1h[8], b1l[8], b3h[8], b3l[8];
            #pragma unroll
            for (int p = 0; p < 2; p++) {
                int nb = wn + p * 16;
                ldsm_x4(&b1h[p * 4], base + 10240 + (nb + b_r) * 40 + kk + b_c);
                ldsm_x4(&b1l[p * 4], base + 12800 + (nb + b_r) * 40 + kk + b_c);
                ldsm_x4(&b3h[p * 4], base + 15360 + (nb + b_r) * 40 + kk + b_c);
                ldsm_x4(&b3l[p * 4], base + 17920 + (nb + b_r) * 40 + kk + b_c);
            }
            #pragma unroll
            for (int mi = 0; mi < 2; mi++)
                #pragma unroll
                for (int ni = 0; ni < 4; ni++) mma_bf16(acc1[mi][ni], ah[mi], &b1h[ni * 2]);
            #pragma unroll
            for (int mi = 0; mi < 2; mi++)
                #pragma unroll
                for (int ni = 0; ni < 4; ni++) mma_bf16(acc3[mi][ni], ah[mi], &b3h[ni * 2]);
            #pragma unroll
            for (int mi = 0; mi < 2; mi++)
                #pragma unroll
                for (int ni = 0; ni < 4; ni++) mma_bf16(acc1[mi][ni], ah[mi], &b1l[ni * 2]);
            #pragma unroll
            for (int mi = 0; mi < 2; mi++)
                #pragma unroll
                for (int ni = 0; ni < 4; ni++) mma_bf16(acc3[mi][ni], ah[mi], &b3l[ni * 2]);
            #pragma unroll
            for (int mi = 0; mi < 2; mi++)
                #pragma unroll
                for (int ni = 0; ni < 4; ni++) mma_bf16(acc1[mi][ni], al[mi], &b1h[ni * 2]);
            #pragma unroll
            for (int mi = 0; mi < 2; mi++)
                #pragma unroll
                for (int ni = 0; ni < 4; ni++) mma_bf16(acc3[mi][ni], al[mi], &b3h[ni * 2]);
        }
        __syncthreads();
    }

    // epilogue: silu(acc1) * acc3 -> bf16 hi/lo planes
    #pragma unroll
    for (int mi = 0; mi < 2; mi++) {
        #pragma unroll
        for (int q2 = 0; q2 < 2; q2++) {
            int r_loc = m0 + wm + mi * 16 + (lane >> 2) + q2 * 8;
            if (r_loc >= count) continue;
            bf16* hrow = g_acth + (size_t)r_loc * FDIM;
            bf16* lrow = g_actl + (size_t)r_loc * FDIM;
            #pragma unroll
            for (int ni = 0; ni < 4; ni++) {
                int c = n0 + wn + ni * 8 + (lane & 3) * 2;
                float a0 = acc1[mi][ni][q2 * 2 + 0];
                float a1 = acc1[mi][ni][q2 * 2 + 1];
                float b0 = acc3[mi][ni][q2 * 2 + 0];
                float b1 = acc3[mi][ni][q2 * 2 + 1];
                float v0 = (a0 / (1.f + __expf(-a0))) * b0;
                float v1 = (a1 / (1.f + __expf(-a1))) * b1;
                bf16 h0 = __float2bfloat16_rn(v0);
                bf16 h1 = __float2bfloat16_rn(v1);
                bf16 l0 = __float2bfloat16_rn(v0 - __bfloat162float(h0));
                bf16 l1 = __float2bfloat16_rn(v1 - __bfloat162float(h1));
                *reinterpret_cast<uint32_t*>(hrow + c) = pack2(h0, h1);
                *reinterpret_cast<uint32_t*>(lrow + c) = pack2(l0, l1);
            }
        }
    }
}

// ---------------- GEMM2: out (+)= w * (act @ w2^T) ----------------
// BM=128, BN=128, BK=32, 2-stage; 8 warps (4 M x 2 N), warp tile 32x64
// smem stage layout: Ah 0, Al 5120, Bh 10240, Bl 15360   (stage = 20480 elems)
#define ST2 20480
__global__ void __launch_bounds__(256) gemm2_kernel(float* __restrict__ OUT, int e)
{
    const int count = (e == NEXP) ? T_TOK : g_cnt[e];
    const int m0 = blockIdx.y * 128;
    if (m0 >= count) return;
    const int n0 = blockIdx.x * 128;

    extern __shared__ __align__(16) bf16 sm[];

    const bf16* Wh = g_w2h + (size_t)e * WSZ;
    const bf16* Wl = g_w2l + (size_t)e * WSZ;

    const int tid  = threadIdx.x;
    const int lane = tid & 31;
    const int warp = tid >> 5;
    const int wm = (warp & 3) * 32;
    const int wn = (warp >> 2) * 64;

    const bf16* srcAh[2]; const bf16* srcAl[2]; int aoff[2]; bool aval[2];
    #pragma unroll
    for (int i = 0; i < 2; i++) {
        int cidx = tid + i * 256;
        int r = cidx >> 2;
        int c8 = (cidx & 3) * 8;
        int gr = m0 + r;
        bool v = gr < count;
        int rr = v ? gr : 0;
        srcAh[i] = g_acth + (size_t)rr * FDIM + c8;
        srcAl[i] = g_actl + (size_t)rr * FDIM + c8;
        aoff[i]  = r * 40 + c8;
        aval[i]  = v;
    }
    size_t bsrc[2]; int boff[2];
    #pragma unroll
    for (int i = 0; i < 2; i++) {
        int cidx = tid + i * 256;
        int r = cidx >> 2;
        int c8 = (cidx & 3) * 8;
        bsrc[i] = (size_t)(n0 + r) * FDIM + c8;
        boff[i] = r * 40 + c8;
    }

    float acc[2][8][4];
    #pragma unroll
    for (int i = 0; i < 2; i++)
        #pragma unroll
        for (int j = 0; j < 8; j++)
            #pragma unroll
            for (int q = 0; q < 4; q++) acc[i][j][q] = 0.f;

    const int a_r = (lane & 7) + ((lane >> 3) & 1) * 8;
    const int a_c = ((lane >> 4) & 1) * 8;
    const int b_r = (lane & 7) + ((lane >> 4) & 1) * 8;
    const int b_c = ((lane >> 3) & 1) * 8;

    const int KT = FDIM / BK;

    auto load_stage = [&](int s, int k0) {
        bf16* base = sm + s * ST2;
        #pragma unroll
        for (int i = 0; i < 2; i++) {
            cp16(base +         aoff[i], srcAh[i] + k0, aval[i]);
            cp16(base +  5120 + aoff[i], srcAl[i] + k0, aval[i]);
            cp16(base + 10240 + boff[i], Wh + bsrc[i] + k0, true);
            cp16(base + 15360 + boff[i], Wl + bsrc[i] + k0, true);
        }
    };

    load_stage(0, 0);
    CP_COMMIT();

    for (int kt = 0; kt < KT; kt++) {
        if (kt + 1 < KT) {
            load_stage((kt + 1) & 1, (kt + 1) * BK);
            CP_COMMIT();
            CP_WAIT(1);
        } else {
            CP_WAIT(0);
        }
        __syncthreads();
        const bf16* base = sm + (kt & 1) * ST2;

        #pragma unroll
        for (int kk = 0; kk < 32; kk += 16) {
            uint32_t ah[2][4], al[2][4];
            ldsm_x4(ah[0], base +        (wm +      a_r) * 40 + kk + a_c);
            ldsm_x4(ah[1], base +        (wm + 16 + a_r) * 40 + kk + a_c);
            ldsm_x4(al[0], base + 5120 + (wm +      a_r) * 40 + kk + a_c);
            ldsm_x4(al[1], base + 5120 + (wm + 16 + a_r) * 40 + kk + a_c);
            uint32_t bh[16], bl[16];
            #pragma unroll
            for (int p = 0; p < 4; p++) {
                int nb = wn + p * 16;
                ldsm_x4(&bh[p * 4], base + 10240 + (nb + b_r) * 40 + kk + b_c);
                ldsm_x4(&bl[p * 4], base + 15360 + (nb + b_r) * 40 + kk + b_c);
            }
            #pragma unroll
            for (int mi = 0; mi < 2; mi++)
                #pragma unroll
                for (int ni = 0; ni < 8; ni++) mma_bf16(acc[mi][ni], ah[mi], &bh[ni * 2]);
            #pragma unroll
            for (int mi = 0; mi < 2; mi++)
                #pragma unroll
                for (int ni = 0; ni < 8; ni++) mma_bf16(acc[mi][ni], ah[mi], &bl[ni * 2]);
            #pragma unroll
            for (int mi = 0; mi < 2; mi++)
                #pragma unroll
                for (int ni = 0; ni < 8; ni++) mma_bf16(acc[mi][ni], al[mi], &bh[ni * 2]);
        }
        __syncthreads();
    }

    #pragma unroll
    for (int mi = 0; mi < 2; mi++) {
        #pragma unroll
        for (int q2 = 0; q2 < 2; q2++) {
            int r_loc = m0 + wm + mi * 16 + (lane >> 2) + q2 * 8;
            if (r_loc >= count) continue;
            if (e == NEXP) {
                float* orow = OUT + (size_t)r_loc * HDIM;
                #pragma unroll
                for (int ni = 0; ni < 8; ni++) {
                    #pragma unroll
                    for (int q1 = 0; q1 < 2; q1++) {
                        int c = n0 + wn + ni * 8 + (lane & 3) * 2 + q1;
                        orow[c] = acc[mi][ni][q2 * 2 + q1];
                    }
                }
            } else {
                int tok = g_list[e][r_loc];
                float wgt = g_wt[e][r_loc];
                float* orow = OUT + (size_t)tok * HDIM;
                #pragma unroll
                for (int ni = 0; ni < 8; ni++) {
                    #pragma unroll
                    for (int q1 = 0; q1 < 2; q1++) {
                        int c = n0 + wn + ni * 8 + (lane & 3) * 2 + q1;
                        atomicAdd(&orow[c], wgt * acc[mi][ni][q2 * 2 + q1]);
                    }
                }
            }
        }
    }
}

// ---------------- launch ----------------
extern "C" void kernel_launch(void* const* d_in, const int* in_sizes, int n_in,
                              void* d_out, int out_size)
{
    const float* x   = (const float*)d_in[0];
    const float* rw  = (const float*)d_in[1];
    const float* rb  = (const float*)d_in[2];
    const float* w1  = (const float*)d_in[3];
    const float* w2  = (const float*)d_in[4];
    const float* w3  = (const float*)d_in[5];
    const float* sw1 = (const float*)d_in[6];
    const float* sw2 = (const float*)d_in[7];
    const float* sw3 = (const float*)d_in[8];

    float* out    = (float*)d_out;
    float* logits = out + (size_t)T_TOK * HDIM;

    static bf16 *p_xh = nullptr, *p_xl, *p_w1h, *p_w1l, *p_w3h, *p_w3l, *p_w2h, *p_w2l;
    static bool init = false;
    if (!init) {
        cudaGetSymbolAddress((void**)&p_xh,  g_xh);
        cudaGetSymbolAddress((void**)&p_xl,  g_xl);
        cudaGetSymbolAddress((void**)&p_w1h, g_w1h);
        cudaGetSymbolAddress((void**)&p_w1l, g_w1l);
        cudaGetSymbolAddress((void**)&p_w3h, g_w3h);
        cudaGetSymbolAddress((void**)&p_w3l, g_w3l);
        cudaGetSymbolAddress((void**)&p_w2h, g_w2h);
        cudaGetSymbolAddress((void**)&p_w2l, g_w2l);
        cudaFuncSetAttribute(gemm13_kernel, cudaFuncAttributeMaxDynamicSharedMemorySize, 2 * ST13 * 2);
        cudaFuncSetAttribute(gemm2_kernel,  cudaFuncAttributeMaxDynamicSharedMemorySize, 2 * ST2 * 2);
        init = true;
    }

    const size_t xn4 = (size_t)T_TOK * HDIM / 4;
    const size_t wn4 = (size_t)NEXP * WSZ / 4;
    const size_t sn4 = WSZ / 4;

    split_arr<<<4096, 256>>>(x, p_xh, p_xl, xn4);
    split_arr<<<8192, 256>>>(w1, p_w1h, p_w1l, wn4);
    split_arr<<<8192, 256>>>(w3, p_w3h, p_w3l, wn4);
    split_arr<<<8192, 256>>>(w2, p_w2h, p_w2l, wn4);
    split_arr<<<2048, 256>>>(sw1, p_w1h + NEXP * WSZ, p_w1l + NEXP * WSZ, sn4);
    split_arr<<<2048, 256>>>(sw3, p_w3h + NEXP * WSZ, p_w3l + NEXP * WSZ, sn4);
    split_arr<<<2048, 256>>>(sw2, p_w2h + NEXP * WSZ, p_w2l + NEXP * WSZ, sn4);

    reset_kernel<<<1, 32>>>();
    router_kernel<<<T_TOK, 256>>>(x, rw, rb, logits);

    dim3 g13(FDIM / 64, T_TOK / 128);   // 64 x 64
    dim3 g2(HDIM / 128, T_TOK / 128);   // 16 x 64
    const int smem13 = 2 * ST13 * 2;
    const int smem2  = 2 * ST2 * 2;

    // shared expert first: plain stores initialize every cell of `out`
    gemm13_kernel<<<g13, 256, smem13>>>(NEXP);
    gemm2_kernel<<<g2, 256, smem2>>>(out, NEXP);

    for (int e = 0; e < NEXP; e++) {
        gemm13_kernel<<<g13, 256, smem13>>>(e);
        gemm2_kernel<<<g2, 256, smem2>>>(out, e);
    }
}

// round 4
// speedup vs baseline: 2.2394x; 1.0011x over previous
#include <cuda_runtime.h>
#include <cuda_bf16.h>
#include <cstdint>

using bf16 = __nv_bfloat16;

#define T_TOK 8192
#define HDIM  2048
#define FDIM  4096
#define NEXP  8
#define BK    32

static const size_t WSZ = (size_t)FDIM * HDIM;

// ---------------- persistent scratch ----------------
__device__ int   g_cnt[NEXP];
__device__ int   g_list[NEXP][T_TOK];
__device__ float g_wt[NEXP][T_TOK];

__device__ bf16 g_xh[(size_t)T_TOK * HDIM];
__device__ bf16 g_xl[(size_t)T_TOK * HDIM];
__device__ bf16 g_w1h[9 * (size_t)FDIM * HDIM];
__device__ bf16 g_w1l[9 * (size_t)FDIM * HDIM];
__device__ bf16 g_w3h[9 * (size_t)FDIM * HDIM];
__device__ bf16 g_w3l[9 * (size_t)FDIM * HDIM];
__device__ bf16 g_w2h[9 * (size_t)FDIM * HDIM];
__device__ bf16 g_w2l[9 * (size_t)FDIM * HDIM];
__device__ bf16 g_acth[(size_t)T_TOK * FDIM];
__device__ bf16 g_actl[(size_t)T_TOK * FDIM];

// ---------------- helpers ----------------
__device__ __forceinline__ uint32_t sm_addr(const void* p) {
    return (uint32_t)__cvta_generic_to_shared(p);
}
__device__ __forceinline__ void ldsm_x4(uint32_t* r, const bf16* p) {
    uint32_t a = sm_addr(p);
    asm volatile("ldmatrix.sync.aligned.m8n8.x4.shared.b16 {%0,%1,%2,%3}, [%4];\n"
                 : "=r"(r[0]), "=r"(r[1]), "=r"(r[2]), "=r"(r[3]) : "r"(a));
}
__device__ __forceinline__ void mma_bf16(float* d, const uint32_t* a, const uint32_t* b) {
    asm volatile(
        "mma.sync.aligned.m16n8k16.row.col.f32.bf16.bf16.f32 "
        "{%0,%1,%2,%3}, {%4,%5,%6,%7}, {%8,%9}, {%0,%1,%2,%3};\n"
        : "+f"(d[0]), "+f"(d[1]), "+f"(d[2]), "+f"(d[3])
        : "r"(a[0]), "r"(a[1]), "r"(a[2]), "r"(a[3]), "r"(b[0]), "r"(b[1]));
}
__device__ __forceinline__ uint32_t pack2(bf16 a, bf16 b) {
    union { __nv_bfloat162 v; uint32_t u; } t;
    t.v.x = a; t.v.y = b;
    return t.u;
}
__device__ __forceinline__ void cp16(bf16* dst, const bf16* src, bool valid) {
    uint32_t d = sm_addr(dst);
    int sz = valid ? 16 : 0;
    asm volatile("cp.async.cg.shared.global [%0], [%1], 16, %2;\n"
                 :: "r"(d), "l"(src), "r"(sz));
}
#define CP_COMMIT() asm volatile("cp.async.commit_group;\n" ::: "memory")
#define CP_WAIT(n)  asm volatile("cp.async.wait_group %0;\n" :: "n"(n) : "memory")

// ---------------- split fp32 -> bf16 hi/lo ----------------
__global__ void __launch_bounds__(256) split_arr(
    const float* __restrict__ src, bf16* __restrict__ hi, bf16* __restrict__ lo, size_t n4)
{
    size_t i = blockIdx.x * (size_t)blockDim.x + threadIdx.x;
    size_t stride = (size_t)gridDim.x * blockDim.x;
    const float4* s4 = (const float4*)src;
    for (; i < n4; i += stride) {
        float4 v = s4[i];
        bf16 h0 = __float2bfloat16_rn(v.x);
        bf16 h1 = __float2bfloat16_rn(v.y);
        bf16 h2 = __float2bfloat16_rn(v.z);
        bf16 h3 = __float2bfloat16_rn(v.w);
        bf16 l0 = __float2bfloat16_rn(v.x - __bfloat162float(h0));
        bf16 l1 = __float2bfloat16_rn(v.y - __bfloat162float(h1));
        bf16 l2 = __float2bfloat16_rn(v.z - __bfloat162float(h2));
        bf16 l3 = __float2bfloat16_rn(v.w - __bfloat162float(h3));
        *reinterpret_cast<uint2*>(hi + i * 4) = make_uint2(pack2(h0, h1), pack2(h2, h3));
        *reinterpret_cast<uint2*>(lo + i * 4) = make_uint2(pack2(l0, l1), pack2(l2, l3));
    }
}

__global__ void reset_kernel() {
    if (threadIdx.x < NEXP) g_cnt[threadIdx.x] = 0;
}

// ---------------- router ----------------
__global__ void __launch_bounds__(256) router_kernel(
    const float* __restrict__ X, const float* __restrict__ RW,
    const float* __restrict__ RB, float* __restrict__ LOG)
{
    __shared__ float sx[HDIM];
    __shared__ float slog[NEXP];
    const int t   = blockIdx.x;
    const int tid = threadIdx.x;

    for (int i = tid; i < HDIM; i += 256) sx[i] = X[(size_t)t * HDIM + i];
    __syncthreads();

    const int w = tid >> 5, lane = tid & 31;
    float s = 0.f;
    const float* rw = RW + (size_t)w * HDIM;
    for (int i = lane; i < HDIM; i += 32) s += sx[i] * rw[i];
    #pragma unroll
    for (int off = 16; off > 0; off >>= 1) s += __shfl_xor_sync(0xffffffffu, s, off);
    if (lane == 0) slog[w] = s + RB[w];
    __syncthreads();

    if (tid == 0) {
        float l[NEXP];
        float m = -1e30f;
        #pragma unroll
        for (int e = 0; e < NEXP; e++) {
            l[e] = slog[e];
            LOG[(size_t)t * NEXP + e] = l[e];
            m = fmaxf(m, l[e]);
        }
        float p[NEXP];
        #pragma unroll
        for (int e = 0; e < NEXP; e++) p[e] = __expf(l[e] - m);
        int i0 = 0;
        #pragma unroll
        for (int e = 1; e < NEXP; e++) if (l[e] > l[i0]) i0 = e;
        int i1 = -1;
        #pragma unroll
        for (int e = 0; e < NEXP; e++) {
            if (e == i0) continue;
            if (i1 < 0 || l[e] > l[i1]) i1 = e;
        }
        float ws = p[i0] + p[i1];
        float w0 = p[i0] / ws, w1 = p[i1] / ws;
        int p0 = atomicAdd(&g_cnt[i0], 1);
        g_list[i0][p0] = t; g_wt[i0][p0] = w0;
        int p1 = atomicAdd(&g_cnt[i1], 1);
        g_list[i1][p1] = t; g_wt[i1][p1] = w1;
    }
}

// ---------------- GEMM13: act = silu(X w1^T) * (X w3^T) ----------------
// BM=128, BN=64, BK=32, 2-stage cp.async; 8 warps (4M x 2N), warp tile 32x32 (dual matrix)
// stage layout (bf16): Ah 0, Al 5120, B1h 10240, B1l 12800, B3h 15360, B3l 17920
#define ST13 20480
__global__ void __launch_bounds__(256, 2) gemm13_kernel(int e)
{
    const int count = (e == NEXP) ? T_TOK : g_cnt[e];
    const int m0 = blockIdx.y * 128;
    if (m0 >= count) return;
    const int n0 = blockIdx.x * 64;

    extern __shared__ __align__(16) bf16 sm[];

    const bf16* __restrict__ W1h = g_w1h + (size_t)e * WSZ;
    const bf16* __restrict__ W1l = g_w1l + (size_t)e * WSZ;
    const bf16* __restrict__ W3h = g_w3h + (size_t)e * WSZ;
    const bf16* __restrict__ W3l = g_w3l + (size_t)e * WSZ;

    const int tid  = threadIdx.x;
    const int lane = tid & 31;
    const int warp = tid >> 5;
    const int wm = (warp & 3) * 32;
    const int wn = (warp >> 2) * 32;

    // compact loader state
    const int ar0 = tid >> 2;           // A row of chunk 0 (chunk 1 = +64)
    const int c8  = (tid & 3) * 8;
    const int aoff0 = ar0 * 40 + c8;
    int  tok0 = 0, tok1 = 0;
    bool av0 = (m0 + ar0) < count;
    bool av1 = (m0 + ar0 + 64) < count;
    if (av0) tok0 = (e == NEXP) ? (m0 + ar0)      : g_list[e][m0 + ar0];
    if (av1) tok1 = (e == NEXP) ? (m0 + ar0 + 64) : g_list[e][m0 + ar0 + 64];
    const size_t asrc0 = (size_t)tok0 * HDIM + c8;
    const size_t asrc1 = (size_t)tok1 * HDIM + c8;
    const size_t bsrc  = (size_t)(n0 + ar0) * HDIM + c8;   // B rows use same r mapping
    const int boff = aoff0;

    float acc1[2][4][4];
    float acc3[2][4][4];
    #pragma unroll
    for (int i = 0; i < 2; i++)
        #pragma unroll
        for (int j = 0; j < 4; j++)
            #pragma unroll
            for (int q = 0; q < 4; q++) { acc1[i][j][q] = 0.f; acc3[i][j][q] = 0.f; }

    const int a_r = (lane & 7) + ((lane >> 3) & 1) * 8;
    const int a_c = ((lane >> 4) & 1) * 8;
    const int b_r = (lane & 7) + ((lane >> 4) & 1) * 8;
    const int b_c = ((lane >> 3) & 1) * 8;

    const int KT = HDIM / BK;

    auto load_stage = [&](int s, int k0) {
        bf16* base = sm + s * ST13;
        cp16(base +         aoff0,      g_xh + asrc0 + k0, av0);
        cp16(base +         aoff0 + 64 * 40, g_xh + asrc1 + k0, av1);
        cp16(base +  5120 + aoff0,      g_xl + asrc0 + k0, av0);
        cp16(base +  5120 + aoff0 + 64 * 40, g_xl + asrc1 + k0, av1);
        cp16(base + 10240 + boff, W1h + bsrc + k0, true);
        cp16(base + 12800 + boff, W1l + bsrc + k0, true);
        cp16(base + 15360 + boff, W3h + bsrc + k0, true);
        cp16(base + 17920 + boff, W3l + bsrc + k0, true);
        CP_COMMIT();
    };

    load_stage(0, 0);

    for (int kt = 0; kt < KT; kt++) {
        if (kt + 1 < KT) {
            load_stage((kt + 1) & 1, (kt + 1) * BK);
            CP_WAIT(1);
        } else {
            CP_WAIT(0);
        }
        __syncthreads();
        const bf16* base = sm + (kt & 1) * ST13;

        #pragma unroll
        for (int kk = 0; kk < 32; kk += 16) {
            uint32_t ah[2][4], al[2][4];
            ldsm_x4(ah[0], base +        (wm +      a_r) * 40 + kk + a_c);
            ldsm_x4(ah[1], base +        (wm + 16 + a_r) * 40 + kk + a_c);
            ldsm_x4(al[0], base + 5120 + (wm +      a_r) * 40 + kk + a_c);
            ldsm_x4(al[1], base + 5120 + (wm + 16 + a_r) * 40 + kk + a_c);

            // matrix 1
            {
                uint32_t bh[8], bl[8];
                #pragma unroll
                for (int p = 0; p < 2; p++) {
                    int nb = wn + p * 16;
                    ldsm_x4(&bh[p * 4], base + 10240 + (nb + b_r) * 40 + kk + b_c);
                    ldsm_x4(&bl[p * 4], base + 12800 + (nb + b_r) * 40 + kk + b_c);
                }
                #pragma unroll
                for (int mi = 0; mi < 2; mi++)
                    #pragma unroll
                    for (int ni = 0; ni < 4; ni++) mma_bf16(acc1[mi][ni], ah[mi], &bh[ni * 2]);
                #pragma unroll
                for (int mi = 0; mi < 2; mi++)
                    #pragma unroll
                    for (int ni = 0; ni < 4; ni++) mma_bf16(acc1[mi][ni], ah[mi], &bl[ni * 2]);
                #pragma unroll
                for (int mi = 0; mi < 2; mi++)
                    #pragma unroll
                    for (int ni = 0; ni < 4; ni++) mma_bf16(acc1[mi][ni], al[mi], &bh[ni * 2]);
            }
            // matrix 3
            {
                uint32_t bh[8], bl[8];
                #pragma unroll
                for (int p = 0; p < 2; p++) {
                    int nb = wn + p * 16;
                    ldsm_x4(&bh[p * 4], base + 15360 + (nb + b_r) * 40 + kk + b_c);
                    ldsm_x4(&bl[p * 4], base + 17920 + (nb + b_r) * 40 + kk + b_c);
                }
                #pragma unroll
                for (int mi = 0; mi < 2; mi++)
                    #pragma unroll
                    for (int ni = 0; ni < 4; ni++) mma_bf16(acc3[mi][ni], ah[mi], &bh[ni * 2]);
                #pragma unroll
                for (int mi = 0; mi < 2; mi++)
                    #pragma unroll
                    for (int ni = 0; ni < 4; ni++) mma_bf16(acc3[mi][ni], ah[mi], &bl[ni * 2]);
                #pragma unroll
                for (int mi = 0; mi < 2; mi++)
                    #pragma unroll
                    for (int ni = 0; ni < 4; ni++) mma_bf16(acc3[mi][ni], al[mi], &bh[ni * 2]);
            }
        }
        __syncthreads();
    }

    // epilogue: silu(acc1) * acc3 -> bf16 hi/lo planes
    #pragma unroll
    for (int mi = 0; mi < 2; mi++) {
        #pragma unroll
        for (int q2 = 0; q2 < 2; q2++) {
            int r_loc = m0 + wm + mi * 16 + (lane >> 2) + q2 * 8;
            if (r_loc >= count) continue;
            bf16* hrow = g_acth + (size_t)r_loc * FDIM;
            bf16* lrow = g_actl + (size_t)r_loc * FDIM;
            #pragma unroll
            for (int ni = 0; ni < 4; ni++) {
                int c = n0 + wn + ni * 8 + (lane & 3) * 2;
                float a0 = acc1[mi][ni][q2 * 2 + 0];
                float a1 = acc1[mi][ni][q2 * 2 + 1];
                float b0 = acc3[mi][ni][q2 * 2 + 0];
                float b1 = acc3[mi][ni][q2 * 2 + 1];
                float v0 = (a0 / (1.f + __expf(-a0))) * b0;
                float v1 = (a1 / (1.f + __expf(-a1))) * b1;
                bf16 h0 = __float2bfloat16_rn(v0);
                bf16 h1 = __float2bfloat16_rn(v1);
                bf16 l0 = __float2bfloat16_rn(v0 - __bfloat162float(h0));
                bf16 l1 = __float2bfloat16_rn(v1 - __bfloat162float(h1));
                *reinterpret_cast<uint32_t*>(hrow + c) = pack2(h0, h1);
                *reinterpret_cast<uint32_t*>(lrow + c) = pack2(l0, l1);
            }
        }
    }
}

// ---------------- GEMM2: out (+)= w * (act @ w2^T) ----------------
// BM=128, BN=128, BK=32, 2-stage; 8 warps (4M x 2N), warp tile 32x64
// stage layout: Ah 0, Al 5120, Bh 10240, Bl 15360  (stage = 20480 elems)
#define ST2 20480
__global__ void __launch_bounds__(256, 2) gemm2_kernel(float* __restrict__ OUT, int e)
{
    const int count = (e == NEXP) ? T_TOK : g_cnt[e];
    const int m0 = blockIdx.y * 128;
    if (m0 >= count) return;
    const int n0 = blockIdx.x * 128;

    extern __shared__ __align__(16) bf16 sm[];

    const bf16* __restrict__ Wh = g_w2h + (size_t)e * WSZ;
    const bf16* __restrict__ Wl = g_w2l + (size_t)e * WSZ;

    const int tid  = threadIdx.x;
    const int lane = tid & 31;
    const int warp = tid >> 5;
    const int wm = (warp & 3) * 32;
    const int wn = (warp >> 2) * 64;

    const int ar0 = tid >> 2;
    const int c8  = (tid & 3) * 8;
    const int aoff0 = ar0 * 40 + c8;
    const bool av0 = (m0 + ar0) < count;
    const bool av1 = (m0 + ar0 + 64) < count;
    const size_t asrc0 = (size_t)(av0 ? (m0 + ar0)      : 0) * FDIM + c8;
    const size_t asrc1 = (size_t)(av1 ? (m0 + ar0 + 64) : 0) * FDIM + c8;
    const size_t bsrc0 = (size_t)(n0 + ar0) * FDIM + c8;
    const size_t bsrc1 = bsrc0 + (size_t)64 * FDIM;

    float acc[2][8][4];
    #pragma unroll
    for (int i = 0; i < 2; i++)
        #pragma unroll
        for (int j = 0; j < 8; j++)
            #pragma unroll
            for (int q = 0; q < 4; q++) acc[i][j][q] = 0.f;

    const int a_r = (lane & 7) + ((lane >> 3) & 1) * 8;
    const int a_c = ((lane >> 4) & 1) * 8;
    const int b_r = (lane & 7) + ((lane >> 4) & 1) * 8;
    const int b_c = ((lane >> 3) & 1) * 8;

    const int KT = FDIM / BK;

    auto load_stage = [&](int s, int k0) {
        bf16* base = sm + s * ST2;
        cp16(base +         aoff0,           g_acth + asrc0 + k0, av0);
        cp16(base +         aoff0 + 64 * 40, g_acth + asrc1 + k0, av1);
        cp16(base +  5120 + aoff0,           g_actl + asrc0 + k0, av0);
        cp16(base +  5120 + aoff0 + 64 * 40, g_actl + asrc1 + k0, av1);
        cp16(base + 10240 + aoff0,           Wh + bsrc0 + k0, true);
        cp16(base + 10240 + aoff0 + 64 * 40, Wh + bsrc1 + k0, true);
        cp16(base + 15360 + aoff0,           Wl + bsrc0 + k0, true);
        cp16(base + 15360 + aoff0 + 64 * 40, Wl + bsrc1 + k0, true);
        CP_COMMIT();
    };

    load_stage(0, 0);

    for (int kt = 0; kt < KT; kt++) {
        if (kt + 1 < KT) {
            load_stage((kt + 1) & 1, (kt + 1) * BK);
            CP_WAIT(1);
        } else {
            CP_WAIT(0);
        }
        __syncthreads();
        const bf16* base = sm + (kt & 1) * ST2;

        #pragma unroll
        for (int kk = 0; kk < 32; kk += 16) {
            uint32_t ah[2][4], al[2][4];
            ldsm_x4(ah[0], base +        (wm +      a_r) * 40 + kk + a_c);
            ldsm_x4(ah[1], base +        (wm + 16 + a_r) * 40 + kk + a_c);
            ldsm_x4(al[0], base + 5120 + (wm +      a_r) * 40 + kk + a_c);
            ldsm_x4(al[1], base + 5120 + (wm + 16 + a_r) * 40 + kk + a_c);

            #pragma unroll
            for (int p = 0; p < 4; p++) {
                int nb = wn + p * 16;
                uint32_t bh[4], bl[4];
                ldsm_x4(bh, base + 10240 + (nb + b_r) * 40 + kk + b_c);
                ldsm_x4(bl, base + 15360 + (nb + b_r) * 40 + kk + b_c);
                #pragma unroll
                for (int mi = 0; mi < 2; mi++) {
                    mma_bf16(acc[mi][p * 2 + 0], ah[mi], &bh[0]);
                    mma_bf16(acc[mi][p * 2 + 1], ah[mi], &bh[2]);
                    mma_bf16(acc[mi][p * 2 + 0], ah[mi], &bl[0]);
                    mma_bf16(acc[mi][p * 2 + 1], ah[mi], &bl[2]);
                    mma_bf16(acc[mi][p * 2 + 0], al[mi], &bh[0]);
                    mma_bf16(acc[mi][p * 2 + 1], al[mi], &bh[2]);
                }
            }
        }
        __syncthreads();
    }

    #pragma unroll
    for (int mi = 0; mi < 2; mi++) {
        #pragma unroll
        for (int q2 = 0; q2 < 2; q2++) {
            int r_loc = m0 + wm + mi * 16 + (lane >> 2) + q2 * 8;
            if (r_loc >= count) continue;
            if (e == NEXP) {
                float* orow = OUT + (size_t)r_loc * HDIM;
                #pragma unroll
                for (int ni = 0; ni < 8; ni++) {
                    #pragma unroll
                    for (int q1 = 0; q1 < 2; q1++) {
                        int c = n0 + wn + ni * 8 + (lane & 3) * 2 + q1;
                        orow[c] = acc[mi][ni][q2 * 2 + q1];
                    }
                }
            } else {
                int tok = g_list[e][r_loc];
                float wgt = g_wt[e][r_loc];
                float* orow = OUT + (size_t)tok * HDIM;
                #pragma unroll
                for (int ni = 0; ni < 8; ni++) {
                    #pragma unroll
                    for (int q1 = 0; q1 < 2; q1++) {
                        int c = n0 + wn + ni * 8 + (lane & 3) * 2 + q1;
                        atomicAdd(&orow[c], wgt * acc[mi][ni][q2 * 2 + q1]);
                    }
                }
            }
        }
    }
}

// ---------------- launch ----------------
extern "C" void kernel_launch(void* const* d_in, const int* in_sizes, int n_in,
                              void* d_out, int out_size)
{
    const float* x   = (const float*)d_in[0];
    const float* rw  = (const float*)d_in[1];
    const float* rb  = (const float*)d_in[2];
    const float* w1  = (const float*)d_in[3];
    const float* w2  = (const float*)d_in[4];
    const float* w3  = (const float*)d_in[5];
    const float* sw1 = (const float*)d_in[6];
    const float* sw2 = (const float*)d_in[7];
    const float* sw3 = (const float*)d_in[8];

    float* out    = (float*)d_out;
    float* logits = out + (size_t)T_TOK * HDIM;

    static bf16 *p_xh = nullptr, *p_xl, *p_w1h, *p_w1l, *p_w3h, *p_w3l, *p_w2h, *p_w2l;
    static bool init = false;
    if (!init) {
        cudaGetSymbolAddress((void**)&p_xh,  g_xh);
        cudaGetSymbolAddress((void**)&p_xl,  g_xl);
        cudaGetSymbolAddress((void**)&p_w1h, g_w1h);
        cudaGetSymbolAddress((void**)&p_w1l, g_w1l);
        cudaGetSymbolAddress((void**)&p_w3h, g_w3h);
        cudaGetSymbolAddress((void**)&p_w3l, g_w3l);
        cudaGetSymbolAddress((void**)&p_w2h, g_w2h);
        cudaGetSymbolAddress((void**)&p_w2l, g_w2l);
        cudaFuncSetAttribute(gemm13_kernel, cudaFuncAttributeMaxDynamicSharedMemorySize, 2 * ST13 * 2);
        cudaFuncSetAttribute(gemm2_kernel,  cudaFuncAttributeMaxDynamicSharedMemorySize, 2 * ST2 * 2);
        init = true;
    }

    const size_t xn4 = (size_t)T_TOK * HDIM / 4;
    const size_t wn4 = (size_t)NEXP * WSZ / 4;
    const size_t sn4 = WSZ / 4;

    split_arr<<<4096, 256>>>(x, p_xh, p_xl, xn4);
    split_arr<<<8192, 256>>>(w1, p_w1h, p_w1l, wn4);
    split_arr<<<8192, 256>>>(w3, p_w3h, p_w3l, wn4);
    split_arr<<<8192, 256>>>(w2, p_w2h, p_w2l, wn4);
    split_arr<<<2048, 256>>>(sw1, p_w1h + NEXP * WSZ, p_w1l + NEXP * WSZ, sn4);
    split_arr<<<2048, 256>>>(sw3, p_w3h + NEXP * WSZ, p_w3l + NEXP * WSZ, sn4);
    split_arr<<<2048, 256>>>(sw2, p_w2h + NEXP * WSZ, p_w2l + NEXP * WSZ, sn4);

    reset_kernel<<<1, 32>>>();
    router_kernel<<<T_TOK, 256>>>(x, rw, rb, logits);

    dim3 g13(FDIM / 64, T_TOK / 128);   // 64 x 64
    dim3 g2(HDIM / 128, T_TOK / 128);   // 16 x 64
    const int smem13 = 2 * ST13 * 2;
    const int smem2  = 2 * ST2 * 2;

    // shared expert first: plain stores initialize every cell of `out`
    gemm13_kernel<<<g13, 256, smem13>>>(NEXP);
    gemm2_kernel<<<g2, 256, smem2>>>(out, NEXP);

    for (int e = 0; e < NEXP; e++) {
        gemm13_kernel<<<g13, 256, smem13>>>(e);
        gemm2_kernel<<<g2, 256, smem2>>>(out, e);
    }
}

// round 5
// speedup vs baseline: 2.8285x; 1.2631x over previous
#include <cuda_runtime.h>
#include <cuda_fp16.h>
#include <cstdint>

using h16 = __half;

#define T_TOK 8192
#define HDIM  2048
#define FDIM  4096
#define NEXP  8
#define BK    32

static const size_t WSZ = (size_t)FDIM * HDIM;

// ---------------- persistent scratch ----------------
__device__ int   g_cnt[NEXP];
__device__ int   g_list[NEXP][T_TOK];
__device__ float g_wt[NEXP][T_TOK];

// X and act: two fp16 planes (hi + residual). Weights: single fp16 plane.
__device__ h16 g_xh[(size_t)T_TOK * HDIM];
__device__ h16 g_xl[(size_t)T_TOK * HDIM];
__device__ h16 g_w1[9 * (size_t)FDIM * HDIM];
__device__ h16 g_w3[9 * (size_t)FDIM * HDIM];
__device__ h16 g_w2[9 * (size_t)FDIM * HDIM];
__device__ h16 g_acth[(size_t)T_TOK * FDIM];
__device__ h16 g_actl[(size_t)T_TOK * FDIM];

// ---------------- helpers ----------------
__device__ __forceinline__ uint32_t sm_addr(const void* p) {
    return (uint32_t)__cvta_generic_to_shared(p);
}
__device__ __forceinline__ void ldsm_x4(uint32_t* r, const h16* p) {
    uint32_t a = sm_addr(p);
    asm volatile("ldmatrix.sync.aligned.m8n8.x4.shared.b16 {%0,%1,%2,%3}, [%4];\n"
                 : "=r"(r[0]), "=r"(r[1]), "=r"(r[2]), "=r"(r[3]) : "r"(a));
}
__device__ __forceinline__ void mma_f16(float* d, const uint32_t* a, const uint32_t* b) {
    asm volatile(
        "mma.sync.aligned.m16n8k16.row.col.f32.f16.f16.f32 "
        "{%0,%1,%2,%3}, {%4,%5,%6,%7}, {%8,%9}, {%0,%1,%2,%3};\n"
        : "+f"(d[0]), "+f"(d[1]), "+f"(d[2]), "+f"(d[3])
        : "r"(a[0]), "r"(a[1]), "r"(a[2]), "r"(a[3]), "r"(b[0]), "r"(b[1]));
}
__device__ __forceinline__ uint32_t pack2h(h16 a, h16 b) {
    union { __half2 v; uint32_t u; } t;
    t.v = __halves2half2(a, b);
    return t.u;
}
__device__ __forceinline__ void cp16(h16* dst, const h16* src, bool valid) {
    uint32_t d = sm_addr(dst);
    int sz = valid ? 16 : 0;
    asm volatile("cp.async.cg.shared.global [%0], [%1], 16, %2;\n"
                 :: "r"(d), "l"(src), "r"(sz));
}
#define CP_COMMIT() asm volatile("cp.async.commit_group;\n" ::: "memory")
#define CP_WAIT(n)  asm volatile("cp.async.wait_group %0;\n" :: "n"(n) : "memory")

// ---------------- split kernels ----------------
__global__ void __launch_bounds__(256) split2_arr(
    const float* __restrict__ src, h16* __restrict__ hi, h16* __restrict__ lo, size_t n4)
{
    size_t i = blockIdx.x * (size_t)blockDim.x + threadIdx.x;
    size_t stride = (size_t)gridDim.x * blockDim.x;
    const float4* s4 = (const float4*)src;
    for (; i < n4; i += stride) {
        float4 v = s4[i];
        h16 h0 = __float2half_rn(v.x);
        h16 h1 = __float2half_rn(v.y);
        h16 h2 = __float2half_rn(v.z);
        h16 h3 = __float2half_rn(v.w);
        h16 l0 = __float2half_rn(v.x - __half2float(h0));
        h16 l1 = __float2half_rn(v.y - __half2float(h1));
        h16 l2 = __float2half_rn(v.z - __half2float(h2));
        h16 l3 = __float2half_rn(v.w - __half2float(h3));
        *reinterpret_cast<uint2*>(hi + i * 4) = make_uint2(pack2h(h0, h1), pack2h(h2, h3));
        *reinterpret_cast<uint2*>(lo + i * 4) = make_uint2(pack2h(l0, l1), pack2h(l2, l3));
    }
}
__global__ void __launch_bounds__(256) split1_arr(
    const float* __restrict__ src, h16* __restrict__ dst, size_t n4)
{
    size_t i = blockIdx.x * (size_t)blockDim.x + threadIdx.x;
    size_t stride = (size_t)gridDim.x * blockDim.x;
    const float4* s4 = (const float4*)src;
    for (; i < n4; i += stride) {
        float4 v = s4[i];
        *reinterpret_cast<uint2*>(dst + i * 4) = make_uint2(
            pack2h(__float2half_rn(v.x), __float2half_rn(v.y)),
            pack2h(__float2half_rn(v.z), __float2half_rn(v.w)));
    }
}

__global__ void reset_kernel() {
    if (threadIdx.x < NEXP) g_cnt[threadIdx.x] = 0;
}

// ---------------- router ----------------
__global__ void __launch_bounds__(256) router_kernel(
    const float* __restrict__ X, const float* __restrict__ RW,
    const float* __restrict__ RB, float* __restrict__ LOG)
{
    __shared__ float sx[HDIM];
    __shared__ float slog[NEXP];
    const int t   = blockIdx.x;
    const int tid = threadIdx.x;

    for (int i = tid; i < HDIM; i += 256) sx[i] = X[(size_t)t * HDIM + i];
    __syncthreads();

    const int w = tid >> 5, lane = tid & 31;
    float s = 0.f;
    const float* rw = RW + (size_t)w * HDIM;
    for (int i = lane; i < HDIM; i += 32) s += sx[i] * rw[i];
    #pragma unroll
    for (int off = 16; off > 0; off >>= 1) s += __shfl_xor_sync(0xffffffffu, s, off);
    if (lane == 0) slog[w] = s + RB[w];
    __syncthreads();

    if (tid == 0) {
        float l[NEXP];
        float m = -1e30f;
        #pragma unroll
        for (int e = 0; e < NEXP; e++) {
            l[e] = slog[e];
            LOG[(size_t)t * NEXP + e] = l[e];
            m = fmaxf(m, l[e]);
        }
        float p[NEXP];
        #pragma unroll
        for (int e = 0; e < NEXP; e++) p[e] = __expf(l[e] - m);
        int i0 = 0;
        #pragma unroll
        for (int e = 1; e < NEXP; e++) if (l[e] > l[i0]) i0 = e;
        int i1 = -1;
        #pragma unroll
        for (int e = 0; e < NEXP; e++) {
            if (e == i0) continue;
            if (i1 < 0 || l[e] > l[i1]) i1 = e;
        }
        float ws = p[i0] + p[i1];
        float w0 = p[i0] / ws, w1 = p[i1] / ws;
        int p0 = atomicAdd(&g_cnt[i0], 1);
        g_list[i0][p0] = t; g_wt[i0][p0] = w0;
        int p1 = atomicAdd(&g_cnt[i1], 1);
        g_list[i1][p1] = t; g_wt[i1][p1] = w1;
    }
}

// ---------------- GEMM13: act = silu(X w1^T) * (X w3^T) ----------------
// BM=128, BN=128 (per matrix), BK=32, 3-stage; 8 warps 4Mx2N, warp tile 32x64 dual-matrix
// stage (halfs): Ah 0, Al 5120, B1 10240, B3 15360 -> 20480 halfs (40KB)
#define S13 20480
__global__ void __launch_bounds__(256) gemm13_kernel(int e)
{
    const int count = (e == NEXP) ? T_TOK : g_cnt[e];
    const int m0 = blockIdx.y * 128;
    if (m0 >= count) return;
    const int n0 = blockIdx.x * 128;

    extern __shared__ __align__(16) h16 sm[];

    const h16* __restrict__ W1 = g_w1 + (size_t)e * WSZ;
    const h16* __restrict__ W3 = g_w3 + (size_t)e * WSZ;

    const int tid  = threadIdx.x;
    const int lane = tid & 31;
    const int warp = tid >> 5;
    const int wm = (warp & 3) * 32;
    const int wn = (warp >> 2) * 64;

    const int ar0 = tid >> 2;            // 0..63
    const int c8  = (tid & 3) * 8;
    bool av0 = (m0 + ar0) < count;
    bool av1 = (m0 + ar0 + 64) < count;
    int tok0 = 0, tok1 = 0;
    if (av0) tok0 = (e == NEXP) ? (m0 + ar0)      : g_list[e][m0 + ar0];
    if (av1) tok1 = (e == NEXP) ? (m0 + ar0 + 64) : g_list[e][m0 + ar0 + 64];
    const size_t asrc0 = (size_t)tok0 * HDIM + c8;
    const size_t asrc1 = (size_t)tok1 * HDIM + c8;
    const size_t bsrc0 = (size_t)(n0 + ar0) * HDIM + c8;
    const size_t bsrc1 = bsrc0 + (size_t)64 * HDIM;
    const int off0 = ar0 * 40 + c8;
    const int off1 = off0 + 64 * 40;

    float acc1[2][8][4];
    float acc3[2][8][4];
    #pragma unroll
    for (int i = 0; i < 2; i++)
        #pragma unroll
        for (int j = 0; j < 8; j++)
            #pragma unroll
            for (int q = 0; q < 4; q++) { acc1[i][j][q] = 0.f; acc3[i][j][q] = 0.f; }

    const int a_r = (lane & 7) + ((lane >> 3) & 1) * 8;
    const int a_c = ((lane >> 4) & 1) * 8;
    const int b_r = (lane & 7) + ((lane >> 4) & 1) * 8;
    const int b_c = ((lane >> 3) & 1) * 8;

    const int KT = HDIM / BK;   // 64

    auto load_stage = [&](int s, int k0) {
        h16* base = sm + s * S13;
        cp16(base +         off0, g_xh + asrc0 + k0, av0);
        cp16(base +         off1, g_xh + asrc1 + k0, av1);
        cp16(base +  5120 + off0, g_xl + asrc0 + k0, av0);
        cp16(base +  5120 + off1, g_xl + asrc1 + k0, av1);
        cp16(base + 10240 + off0, W1 + bsrc0 + k0, true);
        cp16(base + 10240 + off1, W1 + bsrc1 + k0, true);
        cp16(base + 15360 + off0, W3 + bsrc0 + k0, true);
        cp16(base + 15360 + off1, W3 + bsrc1 + k0, true);
        CP_COMMIT();
    };

    load_stage(0, 0);
    load_stage(1, BK);

    for (int kt = 0; kt < KT; kt++) {
        if (kt + 2 < KT) { load_stage((kt + 2) % 3, (kt + 2) * BK); CP_WAIT(2); }
        else if (kt + 1 < KT) { CP_WAIT(1); }
        else { CP_WAIT(0); }
        __syncthreads();
        const h16* base = sm + (kt % 3) * S13;

        #pragma unroll
        for (int kk = 0; kk < 32; kk += 16) {
            uint32_t ah[2][4], al[2][4];
            ldsm_x4(ah[0], base +        (wm +      a_r) * 40 + kk + a_c);
            ldsm_x4(ah[1], base +        (wm + 16 + a_r) * 40 + kk + a_c);
            ldsm_x4(al[0], base + 5120 + (wm +      a_r) * 40 + kk + a_c);
            ldsm_x4(al[1], base + 5120 + (wm + 16 + a_r) * 40 + kk + a_c);

            #pragma unroll
            for (int p = 0; p < 4; p++) {
                uint32_t b1[4];
                ldsm_x4(b1, base + 10240 + (wn + p * 16 + b_r) * 40 + kk + b_c);
                #pragma unroll
                for (int mi = 0; mi < 2; mi++) {
                    mma_f16(acc1[mi][p * 2 + 0], ah[mi], &b1[0]);
                    mma_f16(acc1[mi][p * 2 + 1], ah[mi], &b1[2]);
                    mma_f16(acc1[mi][p * 2 + 0], al[mi], &b1[0]);
                    mma_f16(acc1[mi][p * 2 + 1], al[mi], &b1[2]);
                }
            }
            #pragma unroll
            for (int p = 0; p < 4; p++) {
                uint32_t b3[4];
                ldsm_x4(b3, base + 15360 + (wn + p * 16 + b_r) * 40 + kk + b_c);
                #pragma unroll
                for (int mi = 0; mi < 2; mi++) {
                    mma_f16(acc3[mi][p * 2 + 0], ah[mi], &b3[0]);
                    mma_f16(acc3[mi][p * 2 + 1], ah[mi], &b3[2]);
                    mma_f16(acc3[mi][p * 2 + 0], al[mi], &b3[0]);
                    mma_f16(acc3[mi][p * 2 + 1], al[mi], &b3[2]);
                }
            }
        }
        __syncthreads();
    }

    // epilogue: silu(acc1) * acc3 -> fp16 hi/lo planes
    #pragma unroll
    for (int mi = 0; mi < 2; mi++) {
        #pragma unroll
        for (int q2 = 0; q2 < 2; q2++) {
            int r_loc = m0 + wm + mi * 16 + (lane >> 2) + q2 * 8;
            if (r_loc >= count) continue;
            h16* hrow = g_acth + (size_t)r_loc * FDIM;
            h16* lrow = g_actl + (size_t)r_loc * FDIM;
            #pragma unroll
            for (int ni = 0; ni < 8; ni++) {
                int c = n0 + wn + ni * 8 + (lane & 3) * 2;
                float a0 = acc1[mi][ni][q2 * 2 + 0];
                float a1 = acc1[mi][ni][q2 * 2 + 1];
                float b0 = acc3[mi][ni][q2 * 2 + 0];
                float b1 = acc3[mi][ni][q2 * 2 + 1];
                float v0 = (a0 / (1.f + __expf(-a0))) * b0;
                float v1 = (a1 / (1.f + __expf(-a1))) * b1;
                h16 h0 = __float2half_rn(v0);
                h16 h1 = __float2half_rn(v1);
                h16 l0 = __float2half_rn(v0 - __half2float(h0));
                h16 l1 = __float2half_rn(v1 - __half2float(h1));
                *reinterpret_cast<uint32_t*>(hrow + c) = pack2h(h0, h1);
                *reinterpret_cast<uint32_t*>(lrow + c) = pack2h(l0, l1);
            }
        }
    }
}

// ---------------- GEMM2: out (+)= w * (act @ w2^T) ----------------
// BM=128, BN=256, BK=32, 3-stage; 8 warps 2Mx4N, warp tile 64x64
// stage (halfs): Ah 0, Al 5120, B 10240 -> 20480 halfs (40KB)
#define S2 20480
__global__ void __launch_bounds__(256) gemm2_kernel(float* __restrict__ OUT, int e)
{
    const int count = (e == NEXP) ? T_TOK : g_cnt[e];
    const int m0 = blockIdx.y * 128;
    if (m0 >= count) return;
    const int n0 = blockIdx.x * 256;

    extern __shared__ __align__(16) h16 sm[];

    const h16* __restrict__ W2 = g_w2 + (size_t)e * WSZ;

    const int tid  = threadIdx.x;
    const int lane = tid & 31;
    const int warp = tid >> 5;
    const int wm = (warp & 1) * 64;
    const int wn = (warp >> 1) * 64;

    const int ar0 = tid >> 2;            // 0..63
    const int c8  = (tid & 3) * 8;
    const bool av0 = (m0 + ar0) < count;
    const bool av1 = (m0 + ar0 + 64) < count;
    const size_t asrc0 = (size_t)(av0 ? (m0 + ar0)      : 0) * FDIM + c8;
    const size_t asrc1 = (size_t)(av1 ? (m0 + ar0 + 64) : 0) * FDIM + c8;
    const size_t bs0 = (size_t)(n0 + ar0) * FDIM + c8;
    const int off0 = ar0 * 40 + c8;

    float acc[4][8][4];
    #pragma unroll
    for (int i = 0; i < 4; i++)
        #pragma unroll
        for (int j = 0; j < 8; j++)
            #pragma unroll
            for (int q = 0; q < 4; q++) acc[i][j][q] = 0.f;

    const int a_r = (lane & 7) + ((lane >> 3) & 1) * 8;
    const int a_c = ((lane >> 4) & 1) * 8;
    const int b_r = (lane & 7) + ((lane >> 4) & 1) * 8;
    const int b_c = ((lane >> 3) & 1) * 8;

    const int KT = FDIM / BK;   // 128

    auto load_stage = [&](int s, int k0) {
        h16* base = sm + s * S2;
        cp16(base +        off0,            g_acth + asrc0 + k0, av0);
        cp16(base +        off0 + 64 * 40,  g_acth + asrc1 + k0, av1);
        cp16(base + 5120 + off0,            g_actl + asrc0 + k0, av0);
        cp16(base + 5120 + off0 + 64 * 40,  g_actl + asrc1 + k0, av1);
        #pragma unroll
        for (int j = 0; j < 4; j++)
            cp16(base + 10240 + off0 + j * 64 * 40, W2 + bs0 + (size_t)j * 64 * FDIM + k0, true);
        CP_COMMIT();
    };

    load_stage(0, 0);
    load_stage(1, BK);

    for (int kt = 0; kt < KT; kt++) {
        if (kt + 2 < KT) { load_stage((kt + 2) % 3, (kt + 2) * BK); CP_WAIT(2); }
        else if (kt + 1 < KT) { CP_WAIT(1); }
        else { CP_WAIT(0); }
        __syncthreads();
        const h16* base = sm + (kt % 3) * S2;

        #pragma unroll
        for (int kk = 0; kk < 32; kk += 16) {
            uint32_t ah[4][4], al[4][4];
            #pragma unroll
            for (int mi = 0; mi < 4; mi++) {
                ldsm_x4(ah[mi], base +        (wm + mi * 16 + a_r) * 40 + kk + a_c);
                ldsm_x4(al[mi], base + 5120 + (wm + mi * 16 + a_r) * 40 + kk + a_c);
            }
            #pragma unroll
            for (int p = 0; p < 4; p++) {
                uint32_t b[4];
                ldsm_x4(b, base + 10240 + (wn + p * 16 + b_r) * 40 + kk + b_c);
                #pragma unroll
                for (int mi = 0; mi < 4; mi++) {
                    mma_f16(acc[mi][p * 2 + 0], ah[mi], &b[0]);
                    mma_f16(acc[mi][p * 2 + 1], ah[mi], &b[2]);
                    mma_f16(acc[mi][p * 2 + 0], al[mi], &b[0]);
                    mma_f16(acc[mi][p * 2 + 1], al[mi], &b[2]);
                }
            }
        }
        __syncthreads();
    }

    #pragma unroll
    for (int mi = 0; mi < 4; mi++) {
        #pragma unroll
        for (int q2 = 0; q2 < 2; q2++) {
            int r_loc = m0 + wm + mi * 16 + (lane >> 2) + q2 * 8;
            if (r_loc >= count) continue;
            if (e == NEXP) {
                float* orow = OUT + (size_t)r_loc * HDIM;
                #pragma unroll
                for (int ni = 0; ni < 8; ni++) {
                    #pragma unroll
                    for (int q1 = 0; q1 < 2; q1++) {
                        int c = n0 + wn + ni * 8 + (lane & 3) * 2 + q1;
                        orow[c] = acc[mi][ni][q2 * 2 + q1];
                    }
                }
            } else {
                int tok = g_list[e][r_loc];
                float wgt = g_wt[e][r_loc];
                float* orow = OUT + (size_t)tok * HDIM;
                #pragma unroll
                for (int ni = 0; ni < 8; ni++) {
                    #pragma unroll
                    for (int q1 = 0; q1 < 2; q1++) {
                        int c = n0 + wn + ni * 8 + (lane & 3) * 2 + q1;
                        atomicAdd(&orow[c], wgt * acc[mi][ni][q2 * 2 + q1]);
                    }
                }
            }
        }
    }
}

// ---------------- launch ----------------
extern "C" void kernel_launch(void* const* d_in, const int* in_sizes, int n_in,
                              void* d_out, int out_size)
{
    const float* x   = (const float*)d_in[0];
    const float* rw  = (const float*)d_in[1];
    const float* rb  = (const float*)d_in[2];
    const float* w1  = (const float*)d_in[3];
    const float* w2  = (const float*)d_in[4];
    const float* w3  = (const float*)d_in[5];
    const float* sw1 = (const float*)d_in[6];
    const float* sw2 = (const float*)d_in[7];
    const float* sw3 = (const float*)d_in[8];

    float* out    = (float*)d_out;
    float* logits = out + (size_t)T_TOK * HDIM;

    static h16 *p_xh = nullptr, *p_xl, *p_w1, *p_w3, *p_w2;
    static bool init = false;
    if (!init) {
        cudaGetSymbolAddress((void**)&p_xh, g_xh);
        cudaGetSymbolAddress((void**)&p_xl, g_xl);
        cudaGetSymbolAddress((void**)&p_w1, g_w1);
        cudaGetSymbolAddress((void**)&p_w3, g_w3);
        cudaGetSymbolAddress((void**)&p_w2, g_w2);
        cudaFuncSetAttribute(gemm13_kernel, cudaFuncAttributeMaxDynamicSharedMemorySize, 3 * S13 * 2);
        cudaFuncSetAttribute(gemm2_kernel,  cudaFuncAttributeMaxDynamicSharedMemorySize, 3 * S2 * 2);
        init = true;
    }

    const size_t xn4 = (size_t)T_TOK * HDIM / 4;
    const size_t wn4 = (size_t)NEXP * WSZ / 4;
    const size_t sn4 = WSZ / 4;

    dim3 g13(FDIM / 128, T_TOK / 128);   // 32 x 64
    dim3 g2(HDIM / 256, T_TOK / 128);    // 8 x 64
    const int smem13 = 3 * S13 * 2;
    const int smem2  = 3 * S2 * 2;

    // Launch order arranged so ncu (-s 5) profiles gemm13 (index 5).
    split2_arr<<<4096, 256>>>(x, p_xh, p_xl, xn4);                  // 0
    split1_arr<<<2048, 256>>>(sw1, p_w1 + NEXP * WSZ, sn4);         // 1
    split1_arr<<<2048, 256>>>(sw3, p_w3 + NEXP * WSZ, sn4);         // 2
    reset_kernel<<<1, 32>>>();                                      // 3
    router_kernel<<<T_TOK, 256>>>(x, rw, rb, logits);               // 4
    gemm13_kernel<<<g13, 256, smem13>>>(NEXP);                      // 5  <- profiled
    split1_arr<<<2048, 256>>>(sw2, p_w2 + NEXP * WSZ, sn4);         // 6
    gemm2_kernel<<<g2, 256, smem2>>>(out, NEXP);                    // 7 (plain stores init `out`)
    split1_arr<<<8192, 256>>>(w1, p_w1, wn4);                       // 8
    split1_arr<<<8192, 256>>>(w3, p_w3, wn4);                       // 9
    split1_arr<<<8192, 256>>>(w2, p_w2, wn4);                       // 10

    for (int e = 0; e < NEXP; e++) {
        gemm13_kernel<<<g13, 256, smem13>>>(e);
        gemm2_kernel<<<g2, 256, smem2>>>(out, e);
    }
}

// round 6
// speedup vs baseline: 5.1720x; 1.8285x over previous
#include <cuda_runtime.h>
#include <cuda_fp16.h>
#include <cstdint>

using h16 = __half;

#define T_TOK 8192
#define HDIM  2048
#define FDIM  4096
#define NEXP  8
#define BK    64

static const size_t WSZ = (size_t)FDIM * HDIM;

// ---------------- persistent scratch ----------------
__device__ int   g_cnt[NEXP];
__device__ int   g_list[NEXP][T_TOK];
__device__ float g_wt[NEXP][T_TOK];

// single fp16 plane for everything
__device__ h16 g_x[(size_t)T_TOK * HDIM];
__device__ h16 g_w1[9 * (size_t)FDIM * HDIM];
__device__ h16 g_w3[9 * (size_t)FDIM * HDIM];
__device__ h16 g_w2[9 * (size_t)FDIM * HDIM];
__device__ h16 g_act[(size_t)T_TOK * FDIM];

// ---------------- helpers ----------------
__device__ __forceinline__ uint32_t sm_addr(const void* p) {
    return (uint32_t)__cvta_generic_to_shared(p);
}
__device__ __forceinline__ void ldsm_x4(uint32_t* r, const h16* p) {
    uint32_t a = sm_addr(p);
    asm volatile("ldmatrix.sync.aligned.m8n8.x4.shared.b16 {%0,%1,%2,%3}, [%4];\n"
                 : "=r"(r[0]), "=r"(r[1]), "=r"(r[2]), "=r"(r[3]) : "r"(a));
}
__device__ __forceinline__ void mma_f16(float* d, const uint32_t* a, const uint32_t* b) {
    asm volatile(
        "mma.sync.aligned.m16n8k16.row.col.f32.f16.f16.f32 "
        "{%0,%1,%2,%3}, {%4,%5,%6,%7}, {%8,%9}, {%0,%1,%2,%3};\n"
        : "+f"(d[0]), "+f"(d[1]), "+f"(d[2]), "+f"(d[3])
        : "r"(a[0]), "r"(a[1]), "r"(a[2]), "r"(a[3]), "r"(b[0]), "r"(b[1]));
}
__device__ __forceinline__ uint32_t pack2h(h16 a, h16 b) {
    union { __half2 v; uint32_t u; } t;
    t.v = __halves2half2(a, b);
    return t.u;
}
__device__ __forceinline__ void cp16(h16* dst, const h16* src, bool valid) {
    uint32_t d = sm_addr(dst);
    int sz = valid ? 16 : 0;
    asm volatile("cp.async.cg.shared.global [%0], [%1], 16, %2;\n"
                 :: "r"(d), "l"(src), "r"(sz));
}
#define CP_COMMIT() asm volatile("cp.async.commit_group;\n" ::: "memory")
#define CP_WAIT(n)  asm volatile("cp.async.wait_group %0;\n" :: "n"(n) : "memory")

// ---------------- split fp32 -> fp16 ----------------
__global__ void __launch_bounds__(256) split1_arr(
    const float* __restrict__ src, h16* __restrict__ dst, size_t n4)
{
    size_t i = blockIdx.x * (size_t)blockDim.x + threadIdx.x;
    size_t stride = (size_t)gridDim.x * blockDim.x;
    const float4* s4 = (const float4*)src;
    for (; i < n4; i += stride) {
        float4 v = s4[i];
        *reinterpret_cast<uint2*>(dst + i * 4) = make_uint2(
            pack2h(__float2half_rn(v.x), __float2half_rn(v.y)),
            pack2h(__float2half_rn(v.z), __float2half_rn(v.w)));
    }
}

__global__ void reset_kernel() {
    if (threadIdx.x < NEXP) g_cnt[threadIdx.x] = 0;
}

// ---------------- router ----------------
__global__ void __launch_bounds__(256) router_kernel(
    const float* __restrict__ X, const float* __restrict__ RW,
    const float* __restrict__ RB, float* __restrict__ LOG)
{
    __shared__ float sx[HDIM];
    __shared__ float slog[NEXP];
    const int t   = blockIdx.x;
    const int tid = threadIdx.x;

    for (int i = tid; i < HDIM; i += 256) sx[i] = X[(size_t)t * HDIM + i];
    __syncthreads();

    const int w = tid >> 5, lane = tid & 31;
    float s = 0.f;
    const float* rw = RW + (size_t)w * HDIM;
    for (int i = lane; i < HDIM; i += 32) s += sx[i] * rw[i];
    #pragma unroll
    for (int off = 16; off > 0; off >>= 1) s += __shfl_xor_sync(0xffffffffu, s, off);
    if (lane == 0) slog[w] = s + RB[w];
    __syncthreads();

    if (tid == 0) {
        float l[NEXP];
        float m = -1e30f;
        #pragma unroll
        for (int e = 0; e < NEXP; e++) {
            l[e] = slog[e];
            LOG[(size_t)t * NEXP + e] = l[e];
            m = fmaxf(m, l[e]);
        }
        float p[NEXP];
        #pragma unroll
        for (int e = 0; e < NEXP; e++) p[e] = __expf(l[e] - m);
        int i0 = 0;
        #pragma unroll
        for (int e = 1; e < NEXP; e++) if (l[e] > l[i0]) i0 = e;
        int i1 = -1;
        #pragma unroll
        for (int e = 0; e < NEXP; e++) {
            if (e == i0) continue;
            if (i1 < 0 || l[e] > l[i1]) i1 = e;
        }
        float ws = p[i0] + p[i1];
        float w0 = p[i0] / ws, w1 = p[i1] / ws;
        int p0 = atomicAdd(&g_cnt[i0], 1);
        g_list[i0][p0] = t; g_wt[i0][p0] = w0;
        int p1 = atomicAdd(&g_cnt[i1], 1);
        g_list[i1][p1] = t; g_wt[i1][p1] = w1;
    }
}

// shared tile geometry: A 128x64 (stride 72), B 256x64 (stride 72)
#define A_ST   72
#define A_SZ   (128 * 72)          // 9216 halfs
#define B_SZ   (256 * 72)          // 18432 halfs
#define SSTG   (A_SZ + B_SZ)       // 27648 halfs = 55296 B
#define SMEMB  (3 * SSTG * 2)      // 165888 B

// ---------------- GEMM13: act = silu(X w1^T) * (X w3^T) ----------------
// 512 threads, 16 warps (4M x 4N); warp tile 32 rows x (32 W1-cols + 32 W3-cols)
// CTA tile: M=128, N=128 per matrix; BK=64, 3-stage cp.async
__global__ void __launch_bounds__(512) gemm13_kernel(int e)
{
    const int count = (e == NEXP) ? T_TOK : g_cnt[e];
    const int m0 = blockIdx.y * 128;
    if (m0 >= count) return;
    const int n0 = blockIdx.x * 128;

    extern __shared__ __align__(16) h16 sm[];

    const h16* __restrict__ W1 = g_w1 + (size_t)e * WSZ;
    const h16* __restrict__ W3 = g_w3 + (size_t)e * WSZ;

    const int tid  = threadIdx.x;
    const int lane = tid & 31;
    const int warp = tid >> 5;
    const int wm = (warp & 3) * 32;       // M group
    const int wn = (warp >> 2) * 32;      // N group (per matrix)

    // loader: A chunks tid, tid+512 -> rows r0, r0+64 ; B chunks tid+j*512 -> rows r0+j*64
    const int r0  = tid >> 3;             // 0..63
    const int c16 = tid & 7;
    const int aoff = r0 * A_ST + c16 * 8;

    bool av0 = (m0 + r0) < count;
    bool av1 = (m0 + r0 + 64) < count;
    int tok0 = 0, tok1 = 0;
    if (av0) tok0 = (e == NEXP) ? (m0 + r0)      : g_list[e][m0 + r0];
    if (av1) tok1 = (e == NEXP) ? (m0 + r0 + 64) : g_list[e][m0 + r0 + 64];
    const h16* asrc0 = g_x + (size_t)tok0 * HDIM + c16 * 8;
    const h16* asrc1 = g_x + (size_t)tok1 * HDIM + c16 * 8;
    // B: j=0,1 -> W1 rows n0+r0+j*64 ; j=2,3 -> W3 rows n0+r0+(j-2)*64
    const h16* bsrc0 = W1 + (size_t)(n0 + r0)      * HDIM + c16 * 8;
    const h16* bsrc1 = W1 + (size_t)(n0 + r0 + 64) * HDIM + c16 * 8;
    const h16* bsrc2 = W3 + (size_t)(n0 + r0)      * HDIM + c16 * 8;
    const h16* bsrc3 = W3 + (size_t)(n0 + r0 + 64) * HDIM + c16 * 8;

    float acc1[2][4][4];
    float acc3[2][4][4];
    #pragma unroll
    for (int i = 0; i < 2; i++)
        #pragma unroll
        for (int j = 0; j < 4; j++)
            #pragma unroll
            for (int q = 0; q < 4; q++) { acc1[i][j][q] = 0.f; acc3[i][j][q] = 0.f; }

    const int a_r = (lane & 7) + ((lane >> 3) & 1) * 8;
    const int a_c = ((lane >> 4) & 1) * 8;
    const int b_r = (lane & 7) + ((lane >> 4) & 1) * 8;
    const int b_c = ((lane >> 3) & 1) * 8;

    const int KT = HDIM / BK;   // 32

    auto load_stage = [&](int s, int k0) {
        h16* base = sm + s * SSTG;
        cp16(base + aoff,              asrc0 + k0, av0);
        cp16(base + aoff + 64 * A_ST,  asrc1 + k0, av1);
        h16* bb = base + A_SZ;
        cp16(bb + aoff,                bsrc0 + k0, true);
        cp16(bb + aoff +  64 * A_ST,   bsrc1 + k0, true);
        cp16(bb + aoff + 128 * A_ST,   bsrc2 + k0, true);
        cp16(bb + aoff + 192 * A_ST,   bsrc3 + k0, true);
        CP_COMMIT();
    };

    load_stage(0, 0);
    load_stage(1, BK);

    for (int kt = 0; kt < KT; kt++) {
        if (kt + 2 < KT) { load_stage((kt + 2) % 3, (kt + 2) * BK); CP_WAIT(2); }
        else if (kt + 1 < KT) { CP_WAIT(1); }
        else { CP_WAIT(0); }
        __syncthreads();
        const h16* base = sm + (kt % 3) * SSTG;
        const h16* bB = base + A_SZ;

        #pragma unroll
        for (int kk = 0; kk < BK; kk += 16) {
            uint32_t a[2][4];
            ldsm_x4(a[0], base + (wm +      a_r) * A_ST + kk + a_c);
            ldsm_x4(a[1], base + (wm + 16 + a_r) * A_ST + kk + a_c);
            #pragma unroll
            for (int pb = 0; pb < 2; pb++) {
                uint32_t b1[4], b3[4];
                ldsm_x4(b1, bB + (wn + pb * 16 + b_r) * A_ST + kk + b_c);
                ldsm_x4(b3, bB + (128 + wn + pb * 16 + b_r) * A_ST + kk + b_c);
                #pragma unroll
                for (int mi = 0; mi < 2; mi++) {
                    mma_f16(acc1[mi][pb * 2 + 0], a[mi], &b1[0]);
                    mma_f16(acc1[mi][pb * 2 + 1], a[mi], &b1[2]);
                    mma_f16(acc3[mi][pb * 2 + 0], a[mi], &b3[0]);
                    mma_f16(acc3[mi][pb * 2 + 1], a[mi], &b3[2]);
                }
            }
        }
        __syncthreads();
    }

    // epilogue: silu(acc1) * acc3 -> fp16 act
    #pragma unroll
    for (int mi = 0; mi < 2; mi++) {
        #pragma unroll
        for (int q2 = 0; q2 < 2; q2++) {
            int r_loc = m0 + wm + mi * 16 + (lane >> 2) + q2 * 8;
            if (r_loc >= count) continue;
            h16* arow = g_act + (size_t)r_loc * FDIM;
            #pragma unroll
            for (int ni = 0; ni < 4; ni++) {
                int c = n0 + wn + ni * 8 + (lane & 3) * 2;
                float a0 = acc1[mi][ni][q2 * 2 + 0];
                float a1 = acc1[mi][ni][q2 * 2 + 1];
                float b0 = acc3[mi][ni][q2 * 2 + 0];
                float b1 = acc3[mi][ni][q2 * 2 + 1];
                float v0 = (a0 / (1.f + __expf(-a0))) * b0;
                float v1 = (a1 / (1.f + __expf(-a1))) * b1;
                *reinterpret_cast<uint32_t*>(arow + c) =
                    pack2h(__float2half_rn(v0), __float2half_rn(v1));
            }
        }
    }
}

// ---------------- GEMM2: out (+)= w * (act @ w2^T) ----------------
// 512 threads, 16 warps (4M x 4N); warp tile 32x64; CTA 128x256; BK=64, 3-stage
__global__ void __launch_bounds__(512) gemm2_kernel(float* __restrict__ OUT, int e)
{
    const int count = (e == NEXP) ? T_TOK : g_cnt[e];
    const int m0 = blockIdx.y * 128;
    if (m0 >= count) return;
    const int n0 = blockIdx.x * 256;

    extern __shared__ __align__(16) h16 sm[];

    const h16* __restrict__ W2 = g_w2 + (size_t)e * WSZ;

    const int tid  = threadIdx.x;
    const int lane = tid & 31;
    const int warp = tid >> 5;
    const int wm = (warp & 3) * 32;
    const int wn = (warp >> 2) * 64;

    const int r0  = tid >> 3;
    const int c16 = tid & 7;
    const int aoff = r0 * A_ST + c16 * 8;

    const bool av0 = (m0 + r0) < count;
    const bool av1 = (m0 + r0 + 64) < count;
    const h16* asrc0 = g_act + (size_t)(av0 ? (m0 + r0)      : 0) * FDIM + c16 * 8;
    const h16* asrc1 = g_act + (size_t)(av1 ? (m0 + r0 + 64) : 0) * FDIM + c16 * 8;
    const h16* bsrc0 = W2 + (size_t)(n0 + r0)       * FDIM + c16 * 8;
    const h16* bsrc1 = W2 + (size_t)(n0 + r0 +  64) * FDIM + c16 * 8;
    const h16* bsrc2 = W2 + (size_t)(n0 + r0 + 128) * FDIM + c16 * 8;
    const h16* bsrc3 = W2 + (size_t)(n0 + r0 + 192) * FDIM + c16 * 8;

    float acc[2][8][4];
    #pragma unroll
    for (int i = 0; i < 2; i++)
        #pragma unroll
        for (int j = 0; j < 8; j++)
            #pragma unroll
            for (int q = 0; q < 4; q++) acc[i][j][q] = 0.f;

    const int a_r = (lane & 7) + ((lane >> 3) & 1) * 8;
    const int a_c = ((lane >> 4) & 1) * 8;
    const int b_r = (lane & 7) + ((lane >> 4) & 1) * 8;
    const int b_c = ((lane >> 3) & 1) * 8;

    const int KT = FDIM / BK;   // 64

    auto load_stage = [&](int s, int k0) {
        h16* base = sm + s * SSTG;
        cp16(base + aoff,             asrc0 + k0, av0);
        cp16(base + aoff + 64 * A_ST, asrc1 + k0, av1);
        h16* bb = base + A_SZ;
        cp16(bb + aoff,               bsrc0 + k0, true);
        cp16(bb + aoff +  64 * A_ST,  bsrc1 + k0, true);
        cp16(bb + aoff + 128 * A_ST,  bsrc2 + k0, true);
        cp16(bb + aoff + 192 * A_ST,  bsrc3 + k0, true);
        CP_COMMIT();
    };

    load_stage(0, 0);
    load_stage(1, BK);

    for (int kt = 0; kt < KT; kt++) {
        if (kt + 2 < KT) { load_stage((kt + 2) % 3, (kt + 2) * BK); CP_WAIT(2); }
        else if (kt + 1 < KT) { CP_WAIT(1); }
        else { CP_WAIT(0); }
        __syncthreads();
        const h16* base = sm + (kt % 3) * SSTG;
        const h16* bB = base + A_SZ;

        #pragma unroll
        for (int kk = 0; kk < BK; kk += 16) {
            uint32_t a[2][4];
            ldsm_x4(a[0], base + (wm +      a_r) * A_ST + kk + a_c);
            ldsm_x4(a[1], base + (wm + 16 + a_r) * A_ST + kk + a_c);
            #pragma unroll
            for (int pb = 0; pb < 4; pb++) {
                uint32_t b[4];
                ldsm_x4(b, bB + (wn + pb * 16 + b_r) * A_ST + kk + b_c);
                #pragma unroll
                for (int mi = 0; mi < 2; mi++) {
                    mma_f16(acc[mi][pb * 2 + 0], a[mi], &b[0]);
                    mma_f16(acc[mi][pb * 2 + 1], a[mi], &b[2]);
                }
            }
        }
        __syncthreads();
    }

    #pragma unroll
    for (int mi = 0; mi < 2; mi++) {
        #pragma unroll
        for (int q2 = 0; q2 < 2; q2++) {
            int r_loc = m0 + wm + mi * 16 + (lane >> 2) + q2 * 8;
            if (r_loc >= count) continue;
            if (e == NEXP) {
                float* orow = OUT + (size_t)r_loc * HDIM;
                #pragma unroll
                for (int ni = 0; ni < 8; ni++) {
                    #pragma unroll
                    for (int q1 = 0; q1 < 2; q1++) {
                        int c = n0 + wn + ni * 8 + (lane & 3) * 2 + q1;
                        orow[c] = acc[mi][ni][q2 * 2 + q1];
                    }
                }
            } else {
                int tok = g_list[e][r_loc];
                float wgt = g_wt[e][r_loc];
                float* orow = OUT + (size_t)tok * HDIM;
                #pragma unroll
                for (int ni = 0; ni < 8; ni++) {
                    #pragma unroll
                    for (int q1 = 0; q1 < 2; q1++) {
                        int c = n0 + wn + ni * 8 + (lane & 3) * 2 + q1;
                        atomicAdd(&orow[c], wgt * acc[mi][ni][q2 * 2 + q1]);
                    }
                }
            }
        }
    }
}

// ---------------- launch ----------------
extern "C" void kernel_launch(void* const* d_in, const int* in_sizes, int n_in,
                              void* d_out, int out_size)
{
    const float* x   = (const float*)d_in[0];
    const float* rw  = (const float*)d_in[1];
    const float* rb  = (const float*)d_in[2];
    const float* w1  = (const float*)d_in[3];
    const float* w2  = (const float*)d_in[4];
    const float* w3  = (const float*)d_in[5];
    const float* sw1 = (const float*)d_in[6];
    const float* sw2 = (const float*)d_in[7];
    const float* sw3 = (const float*)d_in[8];

    float* out    = (float*)d_out;
    float* logits = out + (size_t)T_TOK * HDIM;

    static h16 *p_x = nullptr, *p_w1, *p_w3, *p_w2;
    static bool init = false;
    if (!init) {
        cudaGetSymbolAddress((void**)&p_x,  g_x);
        cudaGetSymbolAddress((void**)&p_w1, g_w1);
        cudaGetSymbolAddress((void**)&p_w3, g_w3);
        cudaGetSymbolAddress((void**)&p_w2, g_w2);
        cudaFuncSetAttribute(gemm13_kernel, cudaFuncAttributeMaxDynamicSharedMemorySize, SMEMB);
        cudaFuncSetAttribute(gemm2_kernel,  cudaFuncAttributeMaxDynamicSharedMemorySize, SMEMB);
        init = true;
    }

    const size_t xn4 = (size_t)T_TOK * HDIM / 4;
    const size_t wn4 = (size_t)NEXP * WSZ / 4;
    const size_t sn4 = WSZ / 4;

    dim3 g13(FDIM / 128, T_TOK / 128);   // 32 x 64
    dim3 g2(HDIM / 256, T_TOK / 128);    // 8 x 64

    // Launch order arranged so ncu (-s 5) profiles gemm13 (index 5).
    split1_arr<<<4096, 256>>>(x, p_x, xn4);                        // 0
    split1_arr<<<2048, 256>>>(sw1, p_w1 + NEXP * WSZ, sn4);        // 1
    split1_arr<<<2048, 256>>>(sw3, p_w3 + NEXP * WSZ, sn4);        // 2
    reset_kernel<<<1, 32>>>();                                     // 3
    router_kernel<<<T_TOK, 256>>>(x, rw, rb, logits);              // 4
    gemm13_kernel<<<g13, 512, SMEMB>>>(NEXP);                      // 5  <- profiled
    split1_arr<<<2048, 256>>>(sw2, p_w2 + NEXP * WSZ, sn4);        // 6
    gemm2_kernel<<<g2, 512, SMEMB>>>(out, NEXP);                   // 7 (plain stores init `out`)
    split1_arr<<<8192, 256>>>(w1, p_w1, wn4);                      // 8
    split1_arr<<<8192, 256>>>(w3, p_w3, wn4);                      // 9
    split1_arr<<<8192, 256>>>(w2, p_w2, wn4);                      // 10

    for (int e = 0; e < NEXP; e++) {
        gemm13_kernel<<<g13, 512, SMEMB>>>(e);
        gemm2_kernel<<<g2, 512, SMEMB>>>(out, e);
    }
}

// round 7
// speedup vs baseline: 5.9106x; 1.1428x over previous
#include <cuda_runtime.h>
#include <cuda_fp16.h>
#include <cstdint>

using h16 = __half;

#define T_TOK 8192
#define HDIM  2048
#define FDIM  4096
#define NEXP  8
#define BK    64

static const size_t WSZ = (size_t)FDIM * HDIM;

// ---------------- persistent scratch ----------------
__device__ int   g_cnt[NEXP];
__device__ int   g_list[NEXP][T_TOK];
__device__ float g_wt[NEXP][T_TOK];

__device__ h16 g_x[(size_t)T_TOK * HDIM];
__device__ h16 g_w1[9 * (size_t)FDIM * HDIM];
__device__ h16 g_w3[9 * (size_t)FDIM * HDIM];
__device__ h16 g_w2[9 * (size_t)FDIM * HDIM];
__device__ h16 g_act[9 * (size_t)T_TOK * FDIM];   // per-pass activation planes

// ---------------- helpers ----------------
__device__ __forceinline__ uint32_t sm_addr(const void* p) {
    return (uint32_t)__cvta_generic_to_shared(p);
}
__device__ __forceinline__ void ldsm_x4(uint32_t* r, const h16* p) {
    uint32_t a = sm_addr(p);
    asm volatile("ldmatrix.sync.aligned.m8n8.x4.shared.b16 {%0,%1,%2,%3}, [%4];\n"
                 : "=r"(r[0]), "=r"(r[1]), "=r"(r[2]), "=r"(r[3]) : "r"(a));
}
__device__ __forceinline__ void mma_f16(float* d, const uint32_t* a, const uint32_t* b) {
    asm volatile(
        "mma.sync.aligned.m16n8k16.row.col.f32.f16.f16.f32 "
        "{%0,%1,%2,%3}, {%4,%5,%6,%7}, {%8,%9}, {%0,%1,%2,%3};\n"
        : "+f"(d[0]), "+f"(d[1]), "+f"(d[2]), "+f"(d[3])
        : "r"(a[0]), "r"(a[1]), "r"(a[2]), "r"(a[3]), "r"(b[0]), "r"(b[1]));
}
__device__ __forceinline__ uint32_t pack2h(h16 a, h16 b) {
    union { __half2 v; uint32_t u; } t;
    t.v = __halves2half2(a, b);
    return t.u;
}
__device__ __forceinline__ void cp16(h16* dst, const h16* src, bool valid) {
    uint32_t d = sm_addr(dst);
    int sz = valid ? 16 : 0;
    asm volatile("cp.async.cg.shared.global [%0], [%1], 16, %2;\n"
                 :: "r"(d), "l"(src), "r"(sz));
}
#define CP_COMMIT() asm volatile("cp.async.commit_group;\n" ::: "memory")
#define CP_WAIT(n)  asm volatile("cp.async.wait_group %0;\n" :: "n"(n) : "memory")

// ---------------- split fp32 -> fp16 ----------------
__global__ void __launch_bounds__(256) split1_arr(
    const float* __restrict__ src, h16* __restrict__ dst, size_t n4)
{
    size_t i = blockIdx.x * (size_t)blockDim.x + threadIdx.x;
    size_t stride = (size_t)gridDim.x * blockDim.x;
    const float4* s4 = (const float4*)src;
    for (; i < n4; i += stride) {
        float4 v = s4[i];
        *reinterpret_cast<uint2*>(dst + i * 4) = make_uint2(
            pack2h(__float2half_rn(v.x), __float2half_rn(v.y)),
            pack2h(__float2half_rn(v.z), __float2half_rn(v.w)));
    }
}

__global__ void reset_kernel() {
    if (threadIdx.x < NEXP) g_cnt[threadIdx.x] = 0;
}

// ---------------- router ----------------
__global__ void __launch_bounds__(256) router_kernel(
    const float* __restrict__ X, const float* __restrict__ RW,
    const float* __restrict__ RB, float* __restrict__ LOG)
{
    __shared__ float sx[HDIM];
    __shared__ float slog[NEXP];
    const int t   = blockIdx.x;
    const int tid = threadIdx.x;

    for (int i = tid; i < HDIM; i += 256) sx[i] = X[(size_t)t * HDIM + i];
    __syncthreads();

    const int w = tid >> 5, lane = tid & 31;
    float s = 0.f;
    const float* rw = RW + (size_t)w * HDIM;
    for (int i = lane; i < HDIM; i += 32) s += sx[i] * rw[i];
    #pragma unroll
    for (int off = 16; off > 0; off >>= 1) s += __shfl_xor_sync(0xffffffffu, s, off);
    if (lane == 0) slog[w] = s + RB[w];
    __syncthreads();

    if (tid == 0) {
        float l[NEXP];
        float m = -1e30f;
        #pragma unroll
        for (int e = 0; e < NEXP; e++) {
            l[e] = slog[e];
            LOG[(size_t)t * NEXP + e] = l[e];
            m = fmaxf(m, l[e]);
        }
        float p[NEXP];
        #pragma unroll
        for (int e = 0; e < NEXP; e++) p[e] = __expf(l[e] - m);
        int i0 = 0;
        #pragma unroll
        for (int e = 1; e < NEXP; e++) if (l[e] > l[i0]) i0 = e;
        int i1 = -1;
        #pragma unroll
        for (int e = 0; e < NEXP; e++) {
            if (e == i0) continue;
            if (i1 < 0 || l[e] > l[i1]) i1 = e;
        }
        float ws = p[i0] + p[i1];
        float w0 = p[i0] / ws, w1 = p[i1] / ws;
        int p0 = atomicAdd(&g_cnt[i0], 1);
        g_list[i0][p0] = t; g_wt[i0][p0] = w0;
        int p1 = atomicAdd(&g_cnt[i1], 1);
        g_list[i1][p1] = t; g_wt[i1][p1] = w1;
    }
}

// shared tile geometry: A 128x64 (stride 72), B 256x64 (stride 72)
#define A_ST   72
#define A_SZ   (128 * 72)
#define B_SZ   (256 * 72)
#define SSTG   (A_SZ + B_SZ)       // 27648 halfs = 55296 B
#define SMEMB  (3 * SSTG * 2)      // 165888 B

// ---------------- GEMM13 (all passes): act[z] = silu(X w1^T) * (X w3^T) ----------------
// grid (32, 64, 9); 512 threads, 16 warps (4M x 4N)
__global__ void __launch_bounds__(512) gemm13_kernel()
{
    const int z = blockIdx.z;
    const int count = (z == NEXP) ? T_TOK : g_cnt[z];
    const int m0 = blockIdx.y * 128;
    if (m0 >= count) return;
    const int n0 = blockIdx.x * 128;

    extern __shared__ __align__(16) h16 sm[];

    const h16* __restrict__ W1 = g_w1 + (size_t)z * WSZ;
    const h16* __restrict__ W3 = g_w3 + (size_t)z * WSZ;

    const int tid  = threadIdx.x;
    const int lane = tid & 31;
    const int warp = tid >> 5;
    const int wm = (warp & 3) * 32;
    const int wn = (warp >> 2) * 32;

    const int r0  = tid >> 3;
    const int c16 = tid & 7;
    const int aoff = r0 * A_ST + c16 * 8;

    bool av0 = (m0 + r0) < count;
    bool av1 = (m0 + r0 + 64) < count;
    int tok0 = 0, tok1 = 0;
    if (av0) tok0 = (z == NEXP) ? (m0 + r0)      : g_list[z][m0 + r0];
    if (av1) tok1 = (z == NEXP) ? (m0 + r0 + 64) : g_list[z][m0 + r0 + 64];
    const h16* asrc0 = g_x + (size_t)tok0 * HDIM + c16 * 8;
    const h16* asrc1 = g_x + (size_t)tok1 * HDIM + c16 * 8;
    const h16* bsrc0 = W1 + (size_t)(n0 + r0)      * HDIM + c16 * 8;
    const h16* bsrc1 = W1 + (size_t)(n0 + r0 + 64) * HDIM + c16 * 8;
    const h16* bsrc2 = W3 + (size_t)(n0 + r0)      * HDIM + c16 * 8;
    const h16* bsrc3 = W3 + (size_t)(n0 + r0 + 64) * HDIM + c16 * 8;

    float acc1[2][4][4];
    float acc3[2][4][4];
    #pragma unroll
    for (int i = 0; i < 2; i++)
        #pragma unroll
        for (int j = 0; j < 4; j++)
            #pragma unroll
            for (int q = 0; q < 4; q++) { acc1[i][j][q] = 0.f; acc3[i][j][q] = 0.f; }

    const int a_r = (lane & 7) + ((lane >> 3) & 1) * 8;
    const int a_c = ((lane >> 4) & 1) * 8;
    const int b_r = (lane & 7) + ((lane >> 4) & 1) * 8;
    const int b_c = ((lane >> 3) & 1) * 8;

    const int KT = HDIM / BK;   // 32

    auto load_stage = [&](int s, int k0) {
        h16* base = sm + s * SSTG;
        cp16(base + aoff,              asrc0 + k0, av0);
        cp16(base + aoff + 64 * A_ST,  asrc1 + k0, av1);
        h16* bb = base + A_SZ;
        cp16(bb + aoff,                bsrc0 + k0, true);
        cp16(bb + aoff +  64 * A_ST,   bsrc1 + k0, true);
        cp16(bb + aoff + 128 * A_ST,   bsrc2 + k0, true);
        cp16(bb + aoff + 192 * A_ST,   bsrc3 + k0, true);
        CP_COMMIT();
    };

    load_stage(0, 0);
    load_stage(1, BK);

    for (int kt = 0; kt < KT; kt++) {
        if (kt + 1 < KT) { CP_WAIT(1); } else { CP_WAIT(0); }
        __syncthreads();
        // prefetch after the barrier: all warps are done with stage (kt-1)%3
        if (kt + 2 < KT) load_stage((kt + 2) % 3, (kt + 2) * BK);

        const h16* base = sm + (kt % 3) * SSTG;
        const h16* bB = base + A_SZ;

        #pragma unroll
        for (int kk = 0; kk < BK; kk += 16) {
            uint32_t a[2][4];
            ldsm_x4(a[0], base + (wm +      a_r) * A_ST + kk + a_c);
            ldsm_x4(a[1], base + (wm + 16 + a_r) * A_ST + kk + a_c);
            #pragma unroll
            for (int pb = 0; pb < 2; pb++) {
                uint32_t b1[4], b3[4];
                ldsm_x4(b1, bB + (wn + pb * 16 + b_r) * A_ST + kk + b_c);
                ldsm_x4(b3, bB + (128 + wn + pb * 16 + b_r) * A_ST + kk + b_c);
                #pragma unroll
                for (int mi = 0; mi < 2; mi++) {
                    mma_f16(acc1[mi][pb * 2 + 0], a[mi], &b1[0]);
                    mma_f16(acc1[mi][pb * 2 + 1], a[mi], &b1[2]);
                    mma_f16(acc3[mi][pb * 2 + 0], a[mi], &b3[0]);
                    mma_f16(acc3[mi][pb * 2 + 1], a[mi], &b3[2]);
                }
            }
        }
    }

    // epilogue: silu(acc1) * acc3 -> fp16 act plane z
    h16* actz = g_act + (size_t)z * T_TOK * FDIM;
    #pragma unroll
    for (int mi = 0; mi < 2; mi++) {
        #pragma unroll
        for (int q2 = 0; q2 < 2; q2++) {
            int r_loc = m0 + wm + mi * 16 + (lane >> 2) + q2 * 8;
            if (r_loc >= count) continue;
            h16* arow = actz + (size_t)r_loc * FDIM;
            #pragma unroll
            for (int ni = 0; ni < 4; ni++) {
                int c = n0 + wn + ni * 8 + (lane & 3) * 2;
                float a0 = acc1[mi][ni][q2 * 2 + 0];
                float a1 = acc1[mi][ni][q2 * 2 + 1];
                float b0 = acc3[mi][ni][q2 * 2 + 0];
                float b1 = acc3[mi][ni][q2 * 2 + 1];
                float v0 = (a0 / (1.f + __expf(-a0))) * b0;
                float v1 = (a1 / (1.f + __expf(-a1))) * b1;
                *reinterpret_cast<uint32_t*>(arow + c) =
                    pack2h(__float2half_rn(v0), __float2half_rn(v1));
            }
        }
    }
}

// ---------------- GEMM2: out (+)= w * (act[z] @ w2^T) ----------------
// grid (8, 64, passes); z = zoff + blockIdx.z; z==NEXP -> plain store (shared expert)
__global__ void __launch_bounds__(512) gemm2_kernel(float* __restrict__ OUT, int zoff)
{
    const int z = zoff + blockIdx.z;
    const int count = (z == NEXP) ? T_TOK : g_cnt[z];
    const int m0 = blockIdx.y * 128;
    if (m0 >= count) return;
    const int n0 = blockIdx.x * 256;

    extern __shared__ __align__(16) h16 sm[];

    const h16* __restrict__ W2 = g_w2 + (size_t)z * WSZ;
    const h16* __restrict__ actz = g_act + (size_t)z * T_TOK * FDIM;

    const int tid  = threadIdx.x;
    const int lane = tid & 31;
    const int warp = tid >> 5;
    const int wm = (warp & 3) * 32;
    const int wn = (warp >> 2) * 64;

    const int r0  = tid >> 3;
    const int c16 = tid & 7;
    const int aoff = r0 * A_ST + c16 * 8;

    const bool av0 = (m0 + r0) < count;
    const bool av1 = (m0 + r0 + 64) < count;
    const h16* asrc0 = actz + (size_t)(av0 ? (m0 + r0)      : 0) * FDIM + c16 * 8;
    const h16* asrc1 = actz + (size_t)(av1 ? (m0 + r0 + 64) : 0) * FDIM + c16 * 8;
    const h16* bsrc0 = W2 + (size_t)(n0 + r0)       * FDIM + c16 * 8;
    const h16* bsrc1 = W2 + (size_t)(n0 + r0 +  64) * FDIM + c16 * 8;
    const h16* bsrc2 = W2 + (size_t)(n0 + r0 + 128) * FDIM + c16 * 8;
    const h16* bsrc3 = W2 + (size_t)(n0 + r0 + 192) * FDIM + c16 * 8;

    float acc[2][8][4];
    #pragma unroll
    for (int i = 0; i < 2; i++)
        #pragma unroll
        for (int j = 0; j < 8; j++)
            #pragma unroll
            for (int q = 0; q < 4; q++) acc[i][j][q] = 0.f;

    const int a_r = (lane & 7) + ((lane >> 3) & 1) * 8;
    const int a_c = ((lane >> 4) & 1) * 8;
    const int b_r = (lane & 7) + ((lane >> 4) & 1) * 8;
    const int b_c = ((lane >> 3) & 1) * 8;

    const int KT = FDIM / BK;   // 64

    auto load_stage = [&](int s, int k0) {
        h16* base = sm + s * SSTG;
        cp16(base + aoff,             asrc0 + k0, av0);
        cp16(base + aoff + 64 * A_ST, asrc1 + k0, av1);
        h16* bb = base + A_SZ;
        cp16(bb + aoff,               bsrc0 + k0, true);
        cp16(bb + aoff +  64 * A_ST,  bsrc1 + k0, true);
        cp16(bb + aoff + 128 * A_ST,  bsrc2 + k0, true);
        cp16(bb + aoff + 192 * A_ST,  bsrc3 + k0, true);
        CP_COMMIT();
    };

    load_stage(0, 0);
    load_stage(1, BK);

    for (int kt = 0; kt < KT; kt++) {
        if (kt + 1 < KT) { CP_WAIT(1); } else { CP_WAIT(0); }
        __syncthreads();
        if (kt + 2 < KT) load_stage((kt + 2) % 3, (kt + 2) * BK);

        const h16* base = sm + (kt % 3) * SSTG;
        const h16* bB = base + A_SZ;

        #pragma unroll
        for (int kk = 0; kk < BK; kk += 16) {
            uint32_t a[2][4];
            ldsm_x4(a[0], base + (wm +      a_r) * A_ST + kk + a_c);
            ldsm_x4(a[1], base + (wm + 16 + a_r) * A_ST + kk + a_c);
            #pragma unroll
            for (int pb = 0; pb < 4; pb++) {
                uint32_t b[4];
                ldsm_x4(b, bB + (wn + pb * 16 + b_r) * A_ST + kk + b_c);
                #pragma unroll
                for (int mi = 0; mi < 2; mi++) {
                    mma_f16(acc[mi][pb * 2 + 0], a[mi], &b[0]);
                    mma_f16(acc[mi][pb * 2 + 1], a[mi], &b[2]);
                }
            }
        }
    }

    #pragma unroll
    for (int mi = 0; mi < 2; mi++) {
        #pragma unroll
        for (int q2 = 0; q2 < 2; q2++) {
            int r_loc = m0 + wm + mi * 16 + (lane >> 2) + q2 * 8;
            if (r_loc >= count) continue;
            if (z == NEXP) {
                float* orow = OUT + (size_t)r_loc * HDIM;
                #pragma unroll
                for (int ni = 0; ni < 8; ni++) {
                    #pragma unroll
                    for (int q1 = 0; q1 < 2; q1++) {
                        int c = n0 + wn + ni * 8 + (lane & 3) * 2 + q1;
                        orow[c] = acc[mi][ni][q2 * 2 + q1];
                    }
                }
            } else {
                int tok = g_list[z][r_loc];
                float wgt = g_wt[z][r_loc];
                float* orow = OUT + (size_t)tok * HDIM;
                #pragma unroll
                for (int ni = 0; ni < 8; ni++) {
                    #pragma unroll
                    for (int q1 = 0; q1 < 2; q1++) {
                        int c = n0 + wn + ni * 8 + (lane & 3) * 2 + q1;
                        atomicAdd(&orow[c], wgt * acc[mi][ni][q2 * 2 + q1]);
                    }
                }
            }
        }
    }
}

// ---------------- launch ----------------
extern "C" void kernel_launch(void* const* d_in, const int* in_sizes, int n_in,
                              void* d_out, int out_size)
{
    const float* x   = (const float*)d_in[0];
    const float* rw  = (const float*)d_in[1];
    const float* rb  = (const float*)d_in[2];
    const float* w1  = (const float*)d_in[3];
    const float* w2  = (const float*)d_in[4];
    const float* w3  = (const float*)d_in[5];
    const float* sw1 = (const float*)d_in[6];
    const float* sw2 = (const float*)d_in[7];
    const float* sw3 = (const float*)d_in[8];

    float* out    = (float*)d_out;
    float* logits = out + (size_t)T_TOK * HDIM;

    static h16 *p_x = nullptr, *p_w1, *p_w3, *p_w2;
    static bool init = false;
    if (!init) {
        cudaGetSymbolAddress((void**)&p_x,  g_x);
        cudaGetSymbolAddress((void**)&p_w1, g_w1);
        cudaGetSymbolAddress((void**)&p_w3, g_w3);
        cudaGetSymbolAddress((void**)&p_w2, g_w2);
        cudaFuncSetAttribute(gemm13_kernel, cudaFuncAttributeMaxDynamicSharedMemorySize, SMEMB);
        cudaFuncSetAttribute(gemm2_kernel,  cudaFuncAttributeMaxDynamicSharedMemorySize, SMEMB);
        init = true;
    }

    const size_t xn4 = (size_t)T_TOK * HDIM / 4;
    const size_t wn4 = (size_t)NEXP * WSZ / 4;
    const size_t sn4 = WSZ / 4;

    // conversions + routing
    split1_arr<<<4096, 256>>>(x, p_x, xn4);
    split1_arr<<<8192, 256>>>(w1, p_w1, wn4);
    split1_arr<<<8192, 256>>>(w3, p_w3, wn4);
    split1_arr<<<8192, 256>>>(w2, p_w2, wn4);
    split1_arr<<<2048, 256>>>(sw1, p_w1 + NEXP * WSZ, sn4);
    split1_arr<<<2048, 256>>>(sw3, p_w3 + NEXP * WSZ, sn4);
    split1_arr<<<2048, 256>>>(sw2, p_w2 + NEXP * WSZ, sn4);
    reset_kernel<<<1, 32>>>();
    router_kernel<<<T_TOK, 256>>>(x, rw, rb, logits);

    // all 9 gemm13 passes in one launch
    dim3 g13(FDIM / 128, T_TOK / 128, 9);
    gemm13_kernel<<<g13, 512, SMEMB>>>();

    // shared expert gemm2 first (plain stores initialize `out`), then experts (atomic)
    dim3 g2s(HDIM / 256, T_TOK / 128, 1);
    gemm2_kernel<<<g2s, 512, SMEMB>>>(out, NEXP);
    dim3 g2e(HDIM / 256, T_TOK / 128, NEXP);
    gemm2_kernel<<<g2e, 512, SMEMB>>>(out, 0);
}

// round 8
// speedup vs baseline: 5.9950x; 1.0143x over previous
#include <cuda_runtime.h>
#include <cuda_fp16.h>
#include <cstdint>

using h16 = __half;

#define T_TOK 8192
#define HDIM  2048
#define FDIM  4096
#define NEXP  8
#define BK    64

static const size_t WSZ = (size_t)FDIM * HDIM;

// ---------------- persistent scratch ----------------
__device__ int   g_cnt[NEXP];
__device__ int   g_list[NEXP][T_TOK];
__device__ float g_wt[NEXP][T_TOK];

__device__ h16 g_x[(size_t)T_TOK * HDIM];
__device__ h16 g_w1[9 * (size_t)FDIM * HDIM];
__device__ h16 g_w3[9 * (size_t)FDIM * HDIM];
__device__ h16 g_w2[9 * (size_t)FDIM * HDIM];
__device__ h16 g_act[9 * (size_t)T_TOK * FDIM];

// ---------------- helpers ----------------
__device__ __forceinline__ uint32_t sm_addr(const void* p) {
    return (uint32_t)__cvta_generic_to_shared(p);
}
__device__ __forceinline__ void ldsm_x4(uint32_t* r, const h16* p) {
    uint32_t a = sm_addr(p);
    asm volatile("ldmatrix.sync.aligned.m8n8.x4.shared.b16 {%0,%1,%2,%3}, [%4];\n"
                 : "=r"(r[0]), "=r"(r[1]), "=r"(r[2]), "=r"(r[3]) : "r"(a));
}
__device__ __forceinline__ void mma_f16(float* d, const uint32_t* a, const uint32_t* b) {
    asm volatile(
        "mma.sync.aligned.m16n8k16.row.col.f32.f16.f16.f32 "
        "{%0,%1,%2,%3}, {%4,%5,%6,%7}, {%8,%9}, {%0,%1,%2,%3};\n"
        : "+f"(d[0]), "+f"(d[1]), "+f"(d[2]), "+f"(d[3])
        : "r"(a[0]), "r"(a[1]), "r"(a[2]), "r"(a[3]), "r"(b[0]), "r"(b[1]));
}
__device__ __forceinline__ uint32_t pack2h(h16 a, h16 b) {
    union { __half2 v; uint32_t u; } t;
    t.v = __halves2half2(a, b);
    return t.u;
}
__device__ __forceinline__ void cp16(h16* dst, const h16* src, bool valid) {
    uint32_t d = sm_addr(dst);
    int sz = valid ? 16 : 0;
    asm volatile("cp.async.cg.shared.global [%0], [%1], 16, %2;\n"
                 :: "r"(d), "l"(src), "r"(sz));
}
#define CP_COMMIT() asm volatile("cp.async.commit_group;\n" ::: "memory")
#define CP_WAIT(n)  asm volatile("cp.async.wait_group %0;\n" :: "n"(n) : "memory")

// ---------------- conversion: up to 5 arrays in one launch ----------------
__device__ __forceinline__ void conv_loop(const float* __restrict__ src,
                                          h16* __restrict__ dst, size_t n4)
{
    size_t i = blockIdx.x * (size_t)blockDim.x + threadIdx.x;
    size_t stride = (size_t)gridDim.x * blockDim.x;
    const float4* s4 = (const float4*)src;
    for (; i < n4; i += stride) {
        float4 v = s4[i];
        *reinterpret_cast<uint2*>(dst + i * 4) = make_uint2(
            pack2h(__float2half_rn(v.x), __float2half_rn(v.y)),
            pack2h(__float2half_rn(v.z), __float2half_rn(v.w)));
    }
}

__global__ void __launch_bounds__(256) split5(
    const float* s0, h16* d0, size_t n0,
    const float* s1, h16* d1, size_t n1,
    const float* s2, h16* d2, size_t n2,
    const float* s3, h16* d3, size_t n3,
    const float* s4, h16* d4, size_t n4)
{
    switch (blockIdx.z) {
        case 0: conv_loop(s0, d0, n0); break;
        case 1: conv_loop(s1, d1, n1); break;
        case 2: conv_loop(s2, d2, n2); break;
        case 3: conv_loop(s3, d3, n3); break;
        default: conv_loop(s4, d4, n4); break;
    }
}
__global__ void __launch_bounds__(256) split2(
    const float* s0, h16* d0, size_t n0,
    const float* s1, h16* d1, size_t n1)
{
    if (blockIdx.z == 0) conv_loop(s0, d0, n0);
    else                 conv_loop(s1, d1, n1);
}

__global__ void reset_kernel() {
    if (threadIdx.x < NEXP) g_cnt[threadIdx.x] = 0;
}

__global__ void __launch_bounds__(256) zero_out(float4* __restrict__ out, size_t n4)
{
    size_t i = blockIdx.x * (size_t)blockDim.x + threadIdx.x;
    size_t stride = (size_t)gridDim.x * blockDim.x;
    const float4 z = make_float4(0.f, 0.f, 0.f, 0.f);
    for (; i < n4; i += stride) out[i] = z;
}

// ---------------- router: 4 tokens per block ----------------
__global__ void __launch_bounds__(256) router_kernel(
    const float* __restrict__ X, const float* __restrict__ RW,
    const float* __restrict__ RB, float* __restrict__ LOG)
{
    __shared__ float slog[4][NEXP];
    const int tid  = threadIdx.x;
    const int sub  = tid >> 6;            // 0..3 : token slot
    const int stid = tid & 63;            // 64 threads per token
    const int t    = blockIdx.x * 4 + sub;

    const int w    = stid >> 5;           // 2 experts' partial per warpgroup-of-32
    const int lane = stid & 31;

    const float* xrow = X + (size_t)t * HDIM;
    // each 32-lane group handles experts w, w+2, w+4, w+6
    #pragma unroll
    for (int eo = 0; eo < 4; eo++) {
        int e = w + eo * 2;
        const float* rw = RW + (size_t)e * HDIM;
        float s = 0.f;
        for (int i = lane; i < HDIM; i += 32) s += xrow[i] * rw[i];
        #pragma unroll
        for (int off = 16; off > 0; off >>= 1) s += __shfl_xor_sync(0xffffffffu, s, off);
        if (lane == 0) slog[sub][e] = s + RB[e];
    }
    __syncthreads();

    if (stid == 0) {
        float l[NEXP];
        float m = -1e30f;
        #pragma unroll
        for (int e = 0; e < NEXP; e++) {
            l[e] = slog[sub][e];
            LOG[(size_t)t * NEXP + e] = l[e];
            m = fmaxf(m, l[e]);
        }
        float p[NEXP];
        #pragma unroll
        for (int e = 0; e < NEXP; e++) p[e] = __expf(l[e] - m);
        int i0 = 0;
        #pragma unroll
        for (int e = 1; e < NEXP; e++) if (l[e] > l[i0]) i0 = e;
        int i1 = -1;
        #pragma unroll
        for (int e = 0; e < NEXP; e++) {
            if (e == i0) continue;
            if (i1 < 0 || l[e] > l[i1]) i1 = e;
        }
        float ws = p[i0] + p[i1];
        float w0 = p[i0] / ws, w1 = p[i1] / ws;
        int p0 = atomicAdd(&g_cnt[i0], 1);
        g_list[i0][p0] = t; g_wt[i0][p0] = w0;
        int p1 = atomicAdd(&g_cnt[i1], 1);
        g_list[i1][p1] = t; g_wt[i1][p1] = w1;
    }
}

// shared tile geometry: A 128x64 (stride 72), B 256x64 (stride 72)
#define A_ST   72
#define A_SZ   (128 * 72)
#define B_SZ   (256 * 72)
#define SSTG   (A_SZ + B_SZ)
#define SMEMB  (3 * SSTG * 2)

// ---------------- GEMM13 (all passes): act[z] = silu(X w1^T) * (X w3^T) ----------------
__global__ void __launch_bounds__(512) gemm13_kernel()
{
    const int z = blockIdx.z;
    const int count = (z == NEXP) ? T_TOK : g_cnt[z];
    const int m0 = blockIdx.y * 128;
    if (m0 >= count) return;
    const int n0 = blockIdx.x * 128;

    extern __shared__ __align__(16) h16 sm[];

    const h16* __restrict__ W1 = g_w1 + (size_t)z * WSZ;
    const h16* __restrict__ W3 = g_w3 + (size_t)z * WSZ;

    const int tid  = threadIdx.x;
    const int lane = tid & 31;
    const int warp = tid >> 5;
    const int wm = (warp & 3) * 32;
    const int wn = (warp >> 2) * 32;

    const int r0  = tid >> 3;
    const int c16 = tid & 7;
    const int aoff = r0 * A_ST + c16 * 8;

    bool av0 = (m0 + r0) < count;
    bool av1 = (m0 + r0 + 64) < count;
    int tok0 = 0, tok1 = 0;
    if (av0) tok0 = (z == NEXP) ? (m0 + r0)      : g_list[z][m0 + r0];
    if (av1) tok1 = (z == NEXP) ? (m0 + r0 + 64) : g_list[z][m0 + r0 + 64];
    const h16* asrc0 = g_x + (size_t)tok0 * HDIM + c16 * 8;
    const h16* asrc1 = g_x + (size_t)tok1 * HDIM + c16 * 8;
    const h16* bsrc0 = W1 + (size_t)(n0 + r0)      * HDIM + c16 * 8;
    const h16* bsrc1 = W1 + (size_t)(n0 + r0 + 64) * HDIM + c16 * 8;
    const h16* bsrc2 = W3 + (size_t)(n0 + r0)      * HDIM + c16 * 8;
    const h16* bsrc3 = W3 + (size_t)(n0 + r0 + 64) * HDIM + c16 * 8;

    float acc1[2][4][4];
    float acc3[2][4][4];
    #pragma unroll
    for (int i = 0; i < 2; i++)
        #pragma unroll
        for (int j = 0; j < 4; j++)
            #pragma unroll
            for (int q = 0; q < 4; q++) { acc1[i][j][q] = 0.f; acc3[i][j][q] = 0.f; }

    const int a_r = (lane & 7) + ((lane >> 3) & 1) * 8;
    const int a_c = ((lane >> 4) & 1) * 8;
    const int b_r = (lane & 7) + ((lane >> 4) & 1) * 8;
    const int b_c = ((lane >> 3) & 1) * 8;

    const int KT = HDIM / BK;   // 32

    auto load_stage = [&](int s, int k0) {
        h16* base = sm + s * SSTG;
        cp16(base + aoff,              asrc0 + k0, av0);
        cp16(base + aoff + 64 * A_ST,  asrc1 + k0, av1);
        h16* bb = base + A_SZ;
        cp16(bb + aoff,                bsrc0 + k0, true);
        cp16(bb + aoff +  64 * A_ST,   bsrc1 + k0, true);
        cp16(bb + aoff + 128 * A_ST,   bsrc2 + k0, true);
        cp16(bb + aoff + 192 * A_ST,   bsrc3 + k0, true);
        CP_COMMIT();
    };

    load_stage(0, 0);
    load_stage(1, BK);

    for (int kt = 0; kt < KT; kt++) {
        if (kt + 1 < KT) { CP_WAIT(1); } else { CP_WAIT(0); }
        __syncthreads();
        if (kt + 2 < KT) load_stage((kt + 2) % 3, (kt + 2) * BK);

        const h16* base = sm + (kt % 3) * SSTG;
        const h16* bB = base + A_SZ;

        #pragma unroll
        for (int kk = 0; kk < BK; kk += 16) {
            uint32_t a[2][4];
            ldsm_x4(a[0], base + (wm +      a_r) * A_ST + kk + a_c);
            ldsm_x4(a[1], base + (wm + 16 + a_r) * A_ST + kk + a_c);
            #pragma unroll
            for (int pb = 0; pb < 2; pb++) {
                uint32_t b1[4], b3[4];
                ldsm_x4(b1, bB + (wn + pb * 16 + b_r) * A_ST + kk + b_c);
                ldsm_x4(b3, bB + (128 + wn + pb * 16 + b_r) * A_ST + kk + b_c);
                #pragma unroll
                for (int mi = 0; mi < 2; mi++) {
                    mma_f16(acc1[mi][pb * 2 + 0], a[mi], &b1[0]);
                    mma_f16(acc1[mi][pb * 2 + 1], a[mi], &b1[2]);
                    mma_f16(acc3[mi][pb * 2 + 0], a[mi], &b3[0]);
                    mma_f16(acc3[mi][pb * 2 + 1], a[mi], &b3[2]);
                }
            }
        }
    }

    h16* actz = g_act + (size_t)z * T_TOK * FDIM;
    #pragma unroll
    for (int mi = 0; mi < 2; mi++) {
        #pragma unroll
        for (int q2 = 0; q2 < 2; q2++) {
            int r_loc = m0 + wm + mi * 16 + (lane >> 2) + q2 * 8;
            if (r_loc >= count) continue;
            h16* arow = actz + (size_t)r_loc * FDIM;
            #pragma unroll
            for (int ni = 0; ni < 4; ni++) {
                int c = n0 + wn + ni * 8 + (lane & 3) * 2;
                float a0 = acc1[mi][ni][q2 * 2 + 0];
                float a1 = acc1[mi][ni][q2 * 2 + 1];
                float b0 = acc3[mi][ni][q2 * 2 + 0];
                float b1 = acc3[mi][ni][q2 * 2 + 1];
                float v0 = (a0 / (1.f + __expf(-a0))) * b0;
                float v1 = (a1 / (1.f + __expf(-a1))) * b1;
                *reinterpret_cast<uint32_t*>(arow + c) =
                    pack2h(__float2half_rn(v0), __float2half_rn(v1));
            }
        }
    }
}

// ---------------- GEMM2 (all passes, atomic): out += w * (act[z] @ w2^T) ----------------
__global__ void __launch_bounds__(512) gemm2_kernel(float* __restrict__ OUT)
{
    const int z = blockIdx.z;
    const int count = (z == NEXP) ? T_TOK : g_cnt[z];
    const int m0 = blockIdx.y * 128;
    if (m0 >= count) return;
    const int n0 = blockIdx.x * 256;

    extern __shared__ __align__(16) h16 sm[];

    const h16* __restrict__ W2 = g_w2 + (size_t)z * WSZ;
    const h16* __restrict__ actz = g_act + (size_t)z * T_TOK * FDIM;

    const int tid  = threadIdx.x;
    const int lane = tid & 31;
    const int warp = tid >> 5;
    const int wm = (warp & 3) * 32;
    const int wn = (warp >> 2) * 64;

    const int r0  = tid >> 3;
    const int c16 = tid & 7;
    const int aoff = r0 * A_ST + c16 * 8;

    const bool av0 = (m0 + r0) < count;
    const bool av1 = (m0 + r0 + 64) < count;
    const h16* asrc0 = actz + (size_t)(av0 ? (m0 + r0)      : 0) * FDIM + c16 * 8;
    const h16* asrc1 = actz + (size_t)(av1 ? (m0 + r0 + 64) : 0) * FDIM + c16 * 8;
    const h16* bsrc0 = W2 + (size_t)(n0 + r0)       * FDIM + c16 * 8;
    const h16* bsrc1 = W2 + (size_t)(n0 + r0 +  64) * FDIM + c16 * 8;
    const h16* bsrc2 = W2 + (size_t)(n0 + r0 + 128) * FDIM + c16 * 8;
    const h16* bsrc3 = W2 + (size_t)(n0 + r0 + 192) * FDIM + c16 * 8;

    float acc[2][8][4];
    #pragma unroll
    for (int i = 0; i < 2; i++)
        #pragma unroll
        for (int j = 0; j < 8; j++)
            #pragma unroll
            for (int q = 0; q < 4; q++) acc[i][j][q] = 0.f;

    const int a_r = (lane & 7) + ((lane >> 3) & 1) * 8;
    const int a_c = ((lane >> 4) & 1) * 8;
    const int b_r = (lane & 7) + ((lane >> 4) & 1) * 8;
    const int b_c = ((lane >> 3) & 1) * 8;

    const int KT = FDIM / BK;   // 64

    auto load_stage = [&](int s, int k0) {
        h16* base = sm + s * SSTG;
        cp16(base + aoff,             asrc0 + k0, av0);
        cp16(base + aoff + 64 * A_ST, asrc1 + k0, av1);
        h16* bb = base + A_SZ;
        cp16(bb + aoff,               bsrc0 + k0, true);
        cp16(bb + aoff +  64 * A_ST,  bsrc1 + k0, true);
        cp16(bb + aoff + 128 * A_ST,  bsrc2 + k0, true);
        cp16(bb + aoff + 192 * A_ST,  bsrc3 + k0, true);
        CP_COMMIT();
    };

    load_stage(0, 0);
    load_stage(1, BK);

    for (int kt = 0; kt < KT; kt++) {
        if (kt + 1 < KT) { CP_WAIT(1); } else { CP_WAIT(0); }
        __syncthreads();
        if (kt + 2 < KT) load_stage((kt + 2) % 3, (kt + 2) * BK);

        const h16* base = sm + (kt % 3) * SSTG;
        const h16* bB = base + A_SZ;

        #pragma unroll
        for (int kk = 0; kk < BK; kk += 16) {
            uint32_t a[2][4];
            ldsm_x4(a[0], base + (wm +      a_r) * A_ST + kk + a_c);
            ldsm_x4(a[1], base + (wm + 16 + a_r) * A_ST + kk + a_c);
            #pragma unroll
            for (int pb = 0; pb < 4; pb++) {
                uint32_t b[4];
                ldsm_x4(b, bB + (wn + pb * 16 + b_r) * A_ST + kk + b_c);
                #pragma unroll
                for (int mi = 0; mi < 2; mi++) {
                    mma_f16(acc[mi][pb * 2 + 0], a[mi], &b[0]);
                    mma_f16(acc[mi][pb * 2 + 1], a[mi], &b[2]);
                }
            }
        }
    }

    #pragma unroll
    for (int mi = 0; mi < 2; mi++) {
        #pragma unroll
        for (int q2 = 0; q2 < 2; q2++) {
            int r_loc = m0 + wm + mi * 16 + (lane >> 2) + q2 * 8;
            if (r_loc >= count) continue;
            int tok; float wgt;
            if (z == NEXP) { tok = r_loc; wgt = 1.f; }
            else { tok = g_list[z][r_loc]; wgt = g_wt[z][r_loc]; }
            float* orow = OUT + (size_t)tok * HDIM;
            #pragma unroll
            for (int ni = 0; ni < 8; ni++) {
                #pragma unroll
                for (int q1 = 0; q1 < 2; q1++) {
                    int c = n0 + wn + ni * 8 + (lane & 3) * 2 + q1;
                    atomicAdd(&orow[c], wgt * acc[mi][ni][q2 * 2 + q1]);
                }
            }
        }
    }
}

// ---------------- launch ----------------
extern "C" void kernel_launch(void* const* d_in, const int* in_sizes, int n_in,
                              void* d_out, int out_size)
{
    const float* x   = (const float*)d_in[0];
    const float* rw  = (const float*)d_in[1];
    const float* rb  = (const float*)d_in[2];
    const float* w1  = (const float*)d_in[3];
    const float* w2  = (const float*)d_in[4];
    const float* w3  = (const float*)d_in[5];
    const float* sw1 = (const float*)d_in[6];
    const float* sw2 = (const float*)d_in[7];
    const float* sw3 = (const float*)d_in[8];

    float* out    = (float*)d_out;
    float* logits = out + (size_t)T_TOK * HDIM;

    static h16 *p_x = nullptr, *p_w1, *p_w3, *p_w2;
    static bool init = false;
    if (!init) {
        cudaGetSymbolAddress((void**)&p_x,  g_x);
        cudaGetSymbolAddress((void**)&p_w1, g_w1);
        cudaGetSymbolAddress((void**)&p_w3, g_w3);
        cudaGetSymbolAddress((void**)&p_w2, g_w2);
        cudaFuncSetAttribute(gemm13_kernel, cudaFuncAttributeMaxDynamicSharedMemorySize, SMEMB);
        cudaFuncSetAttribute(gemm2_kernel,  cudaFuncAttributeMaxDynamicSharedMemorySize, SMEMB);
        init = true;
    }

    const size_t xn4 = (size_t)T_TOK * HDIM / 4;
    const size_t wn4 = (size_t)NEXP * WSZ / 4;
    const size_t sn4 = WSZ / 4;

    // launch index:                                                     idx
    reset_kernel<<<1, 32>>>();                                        // 0
    router_kernel<<<T_TOK / 4, 256>>>(x, rw, rb, logits);             // 1
    {
        dim3 g(3072, 1, 5);
        split5<<<g, 256>>>(x,  p_x,  xn4,
                           w1, p_w1, wn4,
                           w3, p_w3, wn4,
                           sw1, p_w1 + NEXP * WSZ, sn4,
                           sw3, p_w3 + NEXP * WSZ, sn4);              // 2
    }
    {
        dim3 g(4096, 1, 2);
        split2<<<g, 256>>>(w2, p_w2, wn4,
                           sw2, p_w2 + NEXP * WSZ, sn4);              // 3
    }
    zero_out<<<2048, 256>>>((float4*)out, (size_t)T_TOK * HDIM / 4);  // 4

    dim3 g13(FDIM / 128, T_TOK / 128, 9);
    gemm13_kernel<<<g13, 512, SMEMB>>>();                             // 5  <- ncu -s 5

    dim3 g2(HDIM / 256, T_TOK / 128, 9);
    gemm2_kernel<<<g2, 512, SMEMB>>>(out);                            // 6
}

// round 9
// speedup vs baseline: 6.0362x; 1.0069x over previous
#include <cuda_runtime.h>
#include <cuda_fp16.h>
#include <cstdint>

using h16 = __half;

#define T_TOK 8192
#define HDIM  2048
#define FDIM  4096
#define NEXP  8
#define BK    64

static const size_t WSZ = (size_t)FDIM * HDIM;

// ---------------- persistent scratch ----------------
__device__ int   g_cnt[NEXP];
__device__ int   g_list[NEXP][T_TOK];
__device__ float g_wt[NEXP][T_TOK];

__device__ h16 g_x[(size_t)T_TOK * HDIM];
__device__ h16 g_w1[9 * (size_t)FDIM * HDIM];
__device__ h16 g_w3[9 * (size_t)FDIM * HDIM];
__device__ h16 g_w2[9 * (size_t)FDIM * HDIM];
__device__ h16 g_act[9 * (size_t)T_TOK * FDIM];

// ---------------- helpers ----------------
__device__ __forceinline__ uint32_t sm_addr(const void* p) {
    return (uint32_t)__cvta_generic_to_shared(p);
}
__device__ __forceinline__ void ldsm_x4(uint32_t* r, const h16* p) {
    uint32_t a = sm_addr(p);
    asm volatile("ldmatrix.sync.aligned.m8n8.x4.shared.b16 {%0,%1,%2,%3}, [%4];\n"
                 : "=r"(r[0]), "=r"(r[1]), "=r"(r[2]), "=r"(r[3]) : "r"(a));
}
__device__ __forceinline__ void mma_f16(float* d, const uint32_t* a, const uint32_t* b) {
    asm volatile(
        "mma.sync.aligned.m16n8k16.row.col.f32.f16.f16.f32 "
        "{%0,%1,%2,%3}, {%4,%5,%6,%7}, {%8,%9}, {%0,%1,%2,%3};\n"
        : "+f"(d[0]), "+f"(d[1]), "+f"(d[2]), "+f"(d[3])
        : "r"(a[0]), "r"(a[1]), "r"(a[2]), "r"(a[3]), "r"(b[0]), "r"(b[1]));
}
__device__ __forceinline__ uint32_t pack2h(h16 a, h16 b) {
    union { __half2 v; uint32_t u; } t;
    t.v = __halves2half2(a, b);
    return t.u;
}
__device__ __forceinline__ void cp16(h16* dst, const h16* src, bool valid) {
    uint32_t d = sm_addr(dst);
    int sz = valid ? 16 : 0;
    asm volatile("cp.async.cg.shared.global [%0], [%1], 16, %2;\n"
                 :: "r"(d), "l"(src), "r"(sz));
}
#define CP_COMMIT() asm volatile("cp.async.commit_group;\n" ::: "memory")
#define CP_WAIT(n)  asm volatile("cp.async.wait_group %0;\n" :: "n"(n) : "memory")

// ---------------- conversions ----------------
__device__ __forceinline__ void conv_loop(const float* __restrict__ src,
                                          h16* __restrict__ dst, size_t n4)
{
    size_t i = blockIdx.x * (size_t)blockDim.x + threadIdx.x;
    size_t stride = (size_t)gridDim.x * blockDim.x;
    const float4* s4 = (const float4*)src;
    for (; i < n4; i += stride) {
        float4 v = s4[i];
        *reinterpret_cast<uint2*>(dst + i * 4) = make_uint2(
            pack2h(__float2half_rn(v.x), __float2half_rn(v.y)),
            pack2h(__float2half_rn(v.z), __float2half_rn(v.w)));
    }
}

__global__ void __launch_bounds__(256) split5(
    const float* s0, h16* d0, size_t n0,
    const float* s1, h16* d1, size_t n1,
    const float* s2, h16* d2, size_t n2,
    const float* s3, h16* d3, size_t n3,
    const float* s4, h16* d4, size_t n4)
{
    switch (blockIdx.z) {
        case 0: conv_loop(s0, d0, n0); break;
        case 1: conv_loop(s1, d1, n1); break;
        case 2: conv_loop(s2, d2, n2); break;
        case 3: conv_loop(s3, d3, n3); break;
        default: conv_loop(s4, d4, n4); break;
    }
}
__global__ void __launch_bounds__(256) split2(
    const float* s0, h16* d0, size_t n0,
    const float* s1, h16* d1, size_t n1)
{
    if (blockIdx.z == 0) conv_loop(s0, d0, n0);
    else                 conv_loop(s1, d1, n1);
}

__global__ void reset_kernel() {
    if (threadIdx.x < NEXP) g_cnt[threadIdx.x] = 0;
}

__global__ void __launch_bounds__(256) zero_out(float4* __restrict__ out, size_t n4)
{
    size_t i = blockIdx.x * (size_t)blockDim.x + threadIdx.x;
    size_t stride = (size_t)gridDim.x * blockDim.x;
    const float4 z = make_float4(0.f, 0.f, 0.f, 0.f);
    for (; i < n4; i += stride) out[i] = z;
}

// ---------------- router: 4 tokens per block ----------------
__global__ void __launch_bounds__(256) router_kernel(
    const float* __restrict__ X, const float* __restrict__ RW,
    const float* __restrict__ RB, float* __restrict__ LOG)
{
    __shared__ float slog[4][NEXP];
    const int tid  = threadIdx.x;
    const int sub  = tid >> 6;
    const int stid = tid & 63;
    const int t    = blockIdx.x * 4 + sub;

    const int w    = stid >> 5;
    const int lane = stid & 31;

    const float* xrow = X + (size_t)t * HDIM;
    #pragma unroll
    for (int eo = 0; eo < 4; eo++) {
        int e = w + eo * 2;
        const float* rw = RW + (size_t)e * HDIM;
        float s = 0.f;
        for (int i = lane; i < HDIM; i += 32) s += xrow[i] * rw[i];
        #pragma unroll
        for (int off = 16; off > 0; off >>= 1) s += __shfl_xor_sync(0xffffffffu, s, off);
        if (lane == 0) slog[sub][e] = s + RB[e];
    }
    __syncthreads();

    if (stid == 0) {
        float l[NEXP];
        float m = -1e30f;
        #pragma unroll
        for (int e = 0; e < NEXP; e++) {
            l[e] = slog[sub][e];
            LOG[(size_t)t * NEXP + e] = l[e];
            m = fmaxf(m, l[e]);
        }
        float p[NEXP];
        #pragma unroll
        for (int e = 0; e < NEXP; e++) p[e] = __expf(l[e] - m);
        int i0 = 0;
        #pragma unroll
        for (int e = 1; e < NEXP; e++) if (l[e] > l[i0]) i0 = e;
        int i1 = -1;
        #pragma unroll
        for (int e = 0; e < NEXP; e++) {
            if (e == i0) continue;
            if (i1 < 0 || l[e] > l[i1]) i1 = e;
        }
        float ws = p[i0] + p[i1];
        float w0 = p[i0] / ws, w1 = p[i1] / ws;
        int p0 = atomicAdd(&g_cnt[i0], 1);
        g_list[i0][p0] = t; g_wt[i0][p0] = w0;
        int p1 = atomicAdd(&g_cnt[i1], 1);
        g_list[i1][p1] = t; g_wt[i1][p1] = w1;
    }
}

// shared tile geometry: A 128x64 (stride 72), B 256x64 (stride 72)
#define A_ST   72
#define A_SZ   (128 * 72)
#define B_SZ   (256 * 72)
#define SSTG   (A_SZ + B_SZ)
#define SMEMB  (3 * SSTG * 2)

// ---------------- GEMM13 (all passes): act[z] = silu(X w1^T) * (X w3^T) ----------------
__global__ void __launch_bounds__(512) gemm13_kernel()
{
    const int z = blockIdx.z;
    const int count = (z == NEXP) ? T_TOK : g_cnt[z];
    const int m0 = blockIdx.y * 128;
    if (m0 >= count) return;
    const int n0 = blockIdx.x * 128;

    extern __shared__ __align__(16) h16 sm[];

    const h16* __restrict__ W1 = g_w1 + (size_t)z * WSZ;
    const h16* __restrict__ W3 = g_w3 + (size_t)z * WSZ;

    const int tid  = threadIdx.x;
    const int lane = tid & 31;
    const int warp = tid >> 5;
    const int wm = (warp & 3) * 32;
    const int wn = (warp >> 2) * 32;

    const int r0  = tid >> 3;
    const int c16 = tid & 7;
    const int aoff = r0 * A_ST + c16 * 8;

    bool av0 = (m0 + r0) < count;
    bool av1 = (m0 + r0 + 64) < count;
    int tok0 = 0, tok1 = 0;
    if (av0) tok0 = (z == NEXP) ? (m0 + r0)      : g_list[z][m0 + r0];
    if (av1) tok1 = (z == NEXP) ? (m0 + r0 + 64) : g_list[z][m0 + r0 + 64];
    const h16* asrc0 = g_x + (size_t)tok0 * HDIM + c16 * 8;
    const h16* asrc1 = g_x + (size_t)tok1 * HDIM + c16 * 8;
    const h16* bsrc0 = W1 + (size_t)(n0 + r0)      * HDIM + c16 * 8;
    const h16* bsrc1 = W1 + (size_t)(n0 + r0 + 64) * HDIM + c16 * 8;
    const h16* bsrc2 = W3 + (size_t)(n0 + r0)      * HDIM + c16 * 8;
    const h16* bsrc3 = W3 + (size_t)(n0 + r0 + 64) * HDIM + c16 * 8;

    float acc1[2][4][4];
    float acc3[2][4][4];
    #pragma unroll
    for (int i = 0; i < 2; i++)
        #pragma unroll
        for (int j = 0; j < 4; j++)
            #pragma unroll
            for (int q = 0; q < 4; q++) { acc1[i][j][q] = 0.f; acc3[i][j][q] = 0.f; }

    const int a_r = (lane & 7) + ((lane >> 3) & 1) * 8;
    const int a_c = ((lane >> 4) & 1) * 8;
    const int b_r = (lane & 7) + ((lane >> 4) & 1) * 8;
    const int b_c = ((lane >> 3) & 1) * 8;

    const int KT = HDIM / BK;   // 32

    auto load_stage = [&](int s, int k0) {
        h16* base = sm + s * SSTG;
        cp16(base + aoff,              asrc0 + k0, av0);
        cp16(base + aoff + 64 * A_ST,  asrc1 + k0, av1);
        h16* bb = base + A_SZ;
        cp16(bb + aoff,                bsrc0 + k0, true);
        cp16(bb + aoff +  64 * A_ST,   bsrc1 + k0, true);
        cp16(bb + aoff + 128 * A_ST,   bsrc2 + k0, true);
        cp16(bb + aoff + 192 * A_ST,   bsrc3 + k0, true);
        CP_COMMIT();
    };

    load_stage(0, 0);
    load_stage(1, BK);

    for (int kt = 0; kt < KT; kt++) {
        if (kt + 1 < KT) { CP_WAIT(1); } else { CP_WAIT(0); }
        __syncthreads();
        if (kt + 2 < KT) load_stage((kt + 2) % 3, (kt + 2) * BK);

        const h16* base = sm + (kt % 3) * SSTG;
        const h16* bB = base + A_SZ;

        #pragma unroll
        for (int kk = 0; kk < BK; kk += 16) {
            uint32_t a[2][4];
            ldsm_x4(a[0], base + (wm +      a_r) * A_ST + kk + a_c);
            ldsm_x4(a[1], base + (wm + 16 + a_r) * A_ST + kk + a_c);
            #pragma unroll
            for (int pb = 0; pb < 2; pb++) {
                uint32_t b1[4], b3[4];
                ldsm_x4(b1, bB + (wn + pb * 16 + b_r) * A_ST + kk + b_c);
                ldsm_x4(b3, bB + (128 + wn + pb * 16 + b_r) * A_ST + kk + b_c);
                #pragma unroll
                for (int mi = 0; mi < 2; mi++) {
                    mma_f16(acc1[mi][pb * 2 + 0], a[mi], &b1[0]);
                    mma_f16(acc1[mi][pb * 2 + 1], a[mi], &b1[2]);
                    mma_f16(acc3[mi][pb * 2 + 0], a[mi], &b3[0]);
                    mma_f16(acc3[mi][pb * 2 + 1], a[mi], &b3[2]);
                }
            }
        }
    }

    h16* actz = g_act + (size_t)z * T_TOK * FDIM;
    #pragma unroll
    for (int mi = 0; mi < 2; mi++) {
        #pragma unroll
        for (int q2 = 0; q2 < 2; q2++) {
            int r_loc = m0 + wm + mi * 16 + (lane >> 2) + q2 * 8;
            if (r_loc >= count) continue;
            h16* arow = actz + (size_t)r_loc * FDIM;
            #pragma unroll
            for (int ni = 0; ni < 4; ni++) {
                int c = n0 + wn + ni * 8 + (lane & 3) * 2;
                float a0 = acc1[mi][ni][q2 * 2 + 0];
                float a1 = acc1[mi][ni][q2 * 2 + 1];
                float b0 = acc3[mi][ni][q2 * 2 + 0];
                float b1 = acc3[mi][ni][q2 * 2 + 1];
                float v0 = (a0 / (1.f + __expf(-a0))) * b0;
                float v1 = (a1 / (1.f + __expf(-a1))) * b1;
                *reinterpret_cast<uint32_t*>(arow + c) =
                    pack2h(__float2half_rn(v0), __float2half_rn(v1));
            }
        }
    }
}

// ---------------- GEMM2 (all passes, atomic): out += w * (act[z] @ w2^T) ----------------
__global__ void __launch_bounds__(512) gemm2_kernel(float* __restrict__ OUT)
{
    const int z = blockIdx.z;
    const int count = (z == NEXP) ? T_TOK : g_cnt[z];
    const int m0 = blockIdx.y * 128;
    if (m0 >= count) return;
    const int n0 = blockIdx.x * 256;

    extern __shared__ __align__(16) h16 sm[];

    const h16* __restrict__ W2 = g_w2 + (size_t)z * WSZ;
    const h16* __restrict__ actz = g_act + (size_t)z * T_TOK * FDIM;

    const int tid  = threadIdx.x;
    const int lane = tid & 31;
    const int warp = tid >> 5;
    const int wm = (warp & 3) * 32;
    const int wn = (warp >> 2) * 64;

    const int r0  = tid >> 3;
    const int c16 = tid & 7;
    const int aoff = r0 * A_ST + c16 * 8;

    const bool av0 = (m0 + r0) < count;
    const bool av1 = (m0 + r0 + 64) < count;
    const h16* asrc0 = actz + (size_t)(av0 ? (m0 + r0)      : 0) * FDIM + c16 * 8;
    const h16* asrc1 = actz + (size_t)(av1 ? (m0 + r0 + 64) : 0) * FDIM + c16 * 8;
    const h16* bsrc0 = W2 + (size_t)(n0 + r0)       * FDIM + c16 * 8;
    const h16* bsrc1 = W2 + (size_t)(n0 + r0 +  64) * FDIM + c16 * 8;
    const h16* bsrc2 = W2 + (size_t)(n0 + r0 + 128) * FDIM + c16 * 8;
    const h16* bsrc3 = W2 + (size_t)(n0 + r0 + 192) * FDIM + c16 * 8;

    float acc[2][8][4];
    #pragma unroll
    for (int i = 0; i < 2; i++)
        #pragma unroll
        for (int j = 0; j < 8; j++)
            #pragma unroll
            for (int q = 0; q < 4; q++) acc[i][j][q] = 0.f;

    const int a_r = (lane & 7) + ((lane >> 3) & 1) * 8;
    const int a_c = ((lane >> 4) & 1) * 8;
    const int b_r = (lane & 7) + ((lane >> 4) & 1) * 8;
    const int b_c = ((lane >> 3) & 1) * 8;

    const int KT = FDIM / BK;   // 64

    auto load_stage = [&](int s, int k0) {
        h16* base = sm + s * SSTG;
        cp16(base + aoff,             asrc0 + k0, av0);
        cp16(base + aoff + 64 * A_ST, asrc1 + k0, av1);
        h16* bb = base + A_SZ;
        cp16(bb + aoff,               bsrc0 + k0, true);
        cp16(bb + aoff +  64 * A_ST,  bsrc1 + k0, true);
        cp16(bb + aoff + 128 * A_ST,  bsrc2 + k0, true);
        cp16(bb + aoff + 192 * A_ST,  bsrc3 + k0, true);
        CP_COMMIT();
    };

    load_stage(0, 0);
    load_stage(1, BK);

    for (int kt = 0; kt < KT; kt++) {
        if (kt + 1 < KT) { CP_WAIT(1); } else { CP_WAIT(0); }
        __syncthreads();
        if (kt + 2 < KT) load_stage((kt + 2) % 3, (kt + 2) * BK);

        const h16* base = sm + (kt % 3) * SSTG;
        const h16* bB = base + A_SZ;

        #pragma unroll
        for (int kk = 0; kk < BK; kk += 16) {
            uint32_t a[2][4];
            ldsm_x4(a[0], base + (wm +      a_r) * A_ST + kk + a_c);
            ldsm_x4(a[1], base + (wm + 16 + a_r) * A_ST + kk + a_c);
            #pragma unroll
            for (int pb = 0; pb < 4; pb++) {
                uint32_t b[4];
                ldsm_x4(b, bB + (wn + pb * 16 + b_r) * A_ST + kk + b_c);
                #pragma unroll
                for (int mi = 0; mi < 2; mi++) {
                    mma_f16(acc[mi][pb * 2 + 0], a[mi], &b[0]);
                    mma_f16(acc[mi][pb * 2 + 1], a[mi], &b[2]);
                }
            }
        }
    }

    #pragma unroll
    for (int mi = 0; mi < 2; mi++) {
        #pragma unroll
        for (int q2 = 0; q2 < 2; q2++) {
            int r_loc = m0 + wm + mi * 16 + (lane >> 2) + q2 * 8;
            if (r_loc >= count) continue;
            int tok; float wgt;
            if (z == NEXP) { tok = r_loc; wgt = 1.f; }
            else { tok = g_list[z][r_loc]; wgt = g_wt[z][r_loc]; }
            float* orow = OUT + (size_t)tok * HDIM;
            #pragma unroll
            for (int ni = 0; ni < 8; ni++) {
                #pragma unroll
                for (int q1 = 0; q1 < 2; q1++) {
                    int c = n0 + wn + ni * 8 + (lane & 3) * 2 + q1;
                    atomicAdd(&orow[c], wgt * acc[mi][ni][q2 * 2 + q1]);
                }
            }
        }
    }
}

// ---------------- launch ----------------
extern "C" void kernel_launch(void* const* d_in, const int* in_sizes, int n_in,
                              void* d_out, int out_size)
{
    const float* x   = (const float*)d_in[0];
    const float* rw  = (const float*)d_in[1];
    const float* rb  = (const float*)d_in[2];
    const float* w1  = (const float*)d_in[3];
    const float* w2  = (const float*)d_in[4];
    const float* w3  = (const float*)d_in[5];
    const float* sw1 = (const float*)d_in[6];
    const float* sw2 = (const float*)d_in[7];
    const float* sw3 = (const float*)d_in[8];

    float* out    = (float*)d_out;
    float* logits = out + (size_t)T_TOK * HDIM;

    static h16 *p_x = nullptr, *p_w1, *p_w3, *p_w2;
    static cudaStream_t sR = nullptr, sS = nullptr;
    static cudaEvent_t ev0 = nullptr, evR = nullptr, evS = nullptr;
    static bool init = false;
    if (!init) {
        cudaGetSymbolAddress((void**)&p_x,  g_x);
        cudaGetSymbolAddress((void**)&p_w1, g_w1);
        cudaGetSymbolAddress((void**)&p_w3, g_w3);
        cudaGetSymbolAddress((void**)&p_w2, g_w2);
        cudaFuncSetAttribute(gemm13_kernel, cudaFuncAttributeMaxDynamicSharedMemorySize, SMEMB);
        cudaFuncSetAttribute(gemm2_kernel,  cudaFuncAttributeMaxDynamicSharedMemorySize, SMEMB);
        cudaStreamCreateWithFlags(&sR, cudaStreamNonBlocking);
        cudaStreamCreateWithFlags(&sS, cudaStreamNonBlocking);
        cudaEventCreateWithFlags(&ev0, cudaEventDisableTiming);
        cudaEventCreateWithFlags(&evR, cudaEventDisableTiming);
        cudaEventCreateWithFlags(&evS, cudaEventDisableTiming);
        init = true;
    }

    const size_t xn4 = (size_t)T_TOK * HDIM / 4;
    const size_t wn4 = (size_t)NEXP * WSZ / 4;
    const size_t sn4 = WSZ / 4;

    // fork side streams from the (captured) default stream
    cudaEventRecord(ev0, 0);
    cudaStreamWaitEvent(sR, ev0, 0);
    cudaStreamWaitEvent(sS, ev0, 0);

    reset_kernel<<<1, 32, 0, sR>>>();                                   // launch 0
    router_kernel<<<T_TOK / 4, 256, 0, sR>>>(x, rw, rb, logits);        // launch 1
    cudaEventRecord(evR, sR);

    {
        dim3 g(4096, 1, 2);
        split2<<<g, 256, 0, sS>>>(w2, p_w2, wn4,
                                  sw2, p_w2 + NEXP * WSZ, sn4);         // launch 2
    }
    zero_out<<<2048, 256, 0, sS>>>((float4*)out,
                                   (size_t)T_TOK * HDIM / 4);           // launch 3
    cudaEventRecord(evS, sS);

    {
        dim3 g(3072, 1, 5);
        split5<<<g, 256>>>(x,  p_x,  xn4,
                           w1, p_w1, wn4,
                           w3, p_w3, wn4,
                           sw1, p_w1 + NEXP * WSZ, sn4,
                           sw3, p_w3 + NEXP * WSZ, sn4);                // launch 4
    }

    cudaStreamWaitEvent(0, evR, 0);   // router/reset done before gemm13
    dim3 g13(FDIM / 128, T_TOK / 128, 9);
    gemm13_kernel<<<g13, 512, SMEMB>>>();                               // launch 5 <- ncu

    cudaStreamWaitEvent(0, evS, 0);   // w2 split + zero done before gemm2
    dim3 g2(HDIM / 256, T_TOK / 128, 9);
    gemm2_kernel<<<g2, 512, SMEMB>>>(out);                              // launch 6
}